// round 10
// baseline (speedup 1.0000x reference)
#include <cuda_runtime.h>
#include <cuda_bf16.h>
#include <math.h>
#include <stdint.h>

#define B_  256
#define T_  256
#define I_  64
#define H_  2048
#define L_  4
#define BH_ (B_ * H_)
#define K2_ 4096

// ---- wave kernel tiling: CTA tile 128x64, K chunk 64 (bf16), 2 stages,
//      2 CTAs per SM ----
#define CHUNK    64
#define PITCH    72                      // bf16 elems per smem row (144B)
#define A_PLANE  (128 * PITCH)           // 9216 elems
#define B_PLANE  (64 * PITCH)            // 4608 elems
#define OFF_AH   0
#define OFF_AL   A_PLANE
#define OFF_BH   (2 * A_PLANE)
#define OFF_BL   (2 * A_PLANE + B_PLANE)
#define STAGE_E  (2 * A_PLANE + 2 * B_PLANE)   // 27648 elems = 55296 B
#define NSTAGE   2
#define DYN_SMEM (NSTAGE * STAGE_E * 2)        // 110592 B -> 2 CTAs/SM
#define WTHREADS 256
#define NCTA     256                     // 4 layers x 2 m x 32 n

// ---- device scratch (allocation-free contract) ----
__device__ float g_XT[(size_t)T_ * B_ * I_];
__device__ float g_XP[(size_t)T_ * B_ * H_];                 // layer-0 input projection
__device__ __nv_bfloat16 g_W0h[(size_t)H_ * H_];
__device__ __nv_bfloat16 g_W0l[(size_t)H_ * H_];
__device__ __nv_bfloat16 g_Wch[(size_t)3 * H_ * K2_];        // [Wih ; Whh] concat, layers 1..3
__device__ __nv_bfloat16 g_Wcl[(size_t)3 * H_ * K2_];
__device__ __nv_bfloat16 g_Hh[(size_t)L_ * 2 * BH_];         // h ping-pong, hi digit
__device__ __nv_bfloat16 g_Hl[(size_t)L_ * 2 * BH_];         // lo digit
__device__ unsigned g_bar;

// ---------------------------------------------------------------------------
// helpers
// ---------------------------------------------------------------------------
__device__ __forceinline__ unsigned sptr(const void* p) {
    return (unsigned)__cvta_generic_to_shared(p);
}
__device__ __forceinline__ void cp16(__nv_bfloat16* s, const __nv_bfloat16* g) {
    asm volatile("cp.async.cg.shared.global [%0], [%1], 16;" :: "r"(sptr(s)), "l"(g));
}
__device__ __forceinline__ void ldsm4(unsigned& r0, unsigned& r1, unsigned& r2,
                                      unsigned& r3, const __nv_bfloat16* p) {
    asm volatile("ldmatrix.sync.aligned.m8n8.x4.shared.b16 {%0,%1,%2,%3}, [%4];"
                 : "=r"(r0), "=r"(r1), "=r"(r2), "=r"(r3) : "r"(sptr(p)));
}
__device__ __forceinline__ void mma16816(float* d, const unsigned* a, const unsigned* b) {
    asm volatile("mma.sync.aligned.m16n8k16.row.col.f32.bf16.bf16.f32 "
                 "{%0,%1,%2,%3}, {%4,%5,%6,%7}, {%8,%9}, {%0,%1,%2,%3};"
                 : "+f"(d[0]), "+f"(d[1]), "+f"(d[2]), "+f"(d[3])
                 : "r"(a[0]), "r"(a[1]), "r"(a[2]), "r"(a[3]), "r"(b[0]), "r"(b[1]));
}
__device__ __forceinline__ void mbar_init(unsigned mbar, unsigned cnt) {
    asm volatile("mbarrier.init.shared.b64 [%0], %1;" :: "r"(mbar), "r"(cnt) : "memory");
}
__device__ __forceinline__ void mbar_arrive(unsigned mbar) {
    asm volatile("mbarrier.arrive.shared.b64 _, [%0];" :: "r"(mbar) : "memory");
}
__device__ __forceinline__ void cp_arrive_noinc(unsigned mbar) {
    asm volatile("cp.async.mbarrier.arrive.noinc.shared.b64 [%0];" :: "r"(mbar) : "memory");
}
__device__ __forceinline__ void mbar_wait(unsigned mbar, unsigned phase) {
    asm volatile(
        "{\n\t.reg .pred P1;\n\t"
        "WAIT_LOOP_%=:\n\t"
        "mbarrier.try_wait.parity.shared.b64 P1, [%0], %1;\n\t"
        "@P1 bra.uni WAIT_DONE_%=;\n\t"
        "bra.uni WAIT_LOOP_%=;\n\t"
        "WAIT_DONE_%=:\n\t}"
        :: "r"(mbar), "r"(phase) : "memory");
}

// ---------------------------------------------------------------------------
// x[B,T,I] -> XT[T,B,I]
// ---------------------------------------------------------------------------
__global__ void transpose_x(const float* __restrict__ x, float* __restrict__ xt) {
    int idx = blockIdx.x * blockDim.x + threadIdx.x;
    int i4 = idx & 15;
    int b  = (idx >> 4) & (B_ - 1);
    int t  = idx >> 12;
    float4 v = *(const float4*)(x + ((size_t)b * T_ + t) * I_ + i4 * 4);
    *(float4*)(xt + ((size_t)t * B_ + b) * I_ + i4 * 4) = v;
}

// ---------------------------------------------------------------------------
// fp32 NT GEMM (layer-0 input projection, K=64): C = A@W^T + bias
// ---------------------------------------------------------------------------
template<int BM, int BN, int BK, int TM, int TN>
__global__ __launch_bounds__((BM / TM) * (BN / TN))
void gemm_nt(const float* __restrict__ A, const float* __restrict__ W,
             const float* __restrict__ bias, float* __restrict__ C,
             int M, int N, int K)
{
    constexpr int NT  = (BM / TM) * (BN / TN);
    constexpr int KV  = BK / 4;
    constexpr int AV  = (BM * BK) / (NT * 4);
    constexpr int BV  = (BN * BK) / (NT * 4);
    constexpr int ARS = NT / KV;

    __shared__ __align__(16) float As[BK][BM + 4];
    __shared__ __align__(16) float Bs[BK][BN + 4];

    const int tid = threadIdx.x;
    const int bm  = blockIdx.y * BM;
    const int bn  = blockIdx.x * BN;
    const int lr = tid / KV;
    const int lc = (tid % KV) * 4;
    const float* Ag = A + (size_t)(bm + lr) * K + lc;
    const float* Wg = W + (size_t)(bn + lr) * K + lc;
    const int tx = tid % (BN / TN);
    const int ty = tid / (BN / TN);

    float acc[TM][TN];
    #pragma unroll
    for (int i = 0; i < TM; i++)
        #pragma unroll
        for (int j = 0; j < TN; j++) acc[i][j] = 0.f;

    float4 ra[AV], rb[BV];
    #pragma unroll
    for (int v = 0; v < AV; v++) ra[v] = *(const float4*)(Ag + (size_t)v * ARS * K);
    #pragma unroll
    for (int v = 0; v < BV; v++) rb[v] = *(const float4*)(Wg + (size_t)v * ARS * K);

    for (int k0 = 0; k0 < K; k0 += BK) {
        __syncthreads();
        #pragma unroll
        for (int v = 0; v < AV; v++) {
            As[lc + 0][lr + v * ARS] = ra[v].x; As[lc + 1][lr + v * ARS] = ra[v].y;
            As[lc + 2][lr + v * ARS] = ra[v].z; As[lc + 3][lr + v * ARS] = ra[v].w;
        }
        #pragma unroll
        for (int v = 0; v < BV; v++) {
            Bs[lc + 0][lr + v * ARS] = rb[v].x; Bs[lc + 1][lr + v * ARS] = rb[v].y;
            Bs[lc + 2][lr + v * ARS] = rb[v].z; Bs[lc + 3][lr + v * ARS] = rb[v].w;
        }
        __syncthreads();
        if (k0 + BK < K) {
            #pragma unroll
            for (int v = 0; v < AV; v++) ra[v] = *(const float4*)(Ag + (size_t)v * ARS * K + k0 + BK);
            #pragma unroll
            for (int v = 0; v < BV; v++) rb[v] = *(const float4*)(Wg + (size_t)v * ARS * K + k0 + BK);
        }
        #pragma unroll
        for (int kk = 0; kk < BK; ++kk) {
            float a[TM], b[TN];
            #pragma unroll
            for (int i = 0; i < TM; i += 4) *(float4*)&a[i] = *(const float4*)&As[kk][ty * TM + i];
            #pragma unroll
            for (int j = 0; j < TN; j += 4) *(float4*)&b[j] = *(const float4*)&Bs[kk][tx * TN + j];
            #pragma unroll
            for (int i = 0; i < TM; i++)
                #pragma unroll
                for (int j = 0; j < TN; j++) acc[i][j] = fmaf(a[i], b[j], acc[i][j]);
        }
    }
    const int n0 = bn + tx * TN;
    float4 bia = *(const float4*)(bias + n0);
    #pragma unroll
    for (int i = 0; i < TM; i++) {
        const size_t row = (size_t)(bm + ty * TM + i) * N + n0;
        float4 v;
        v.x = acc[i][0] + bia.x; v.y = acc[i][1] + bia.y;
        v.z = acc[i][2] + bia.z; v.w = acc[i][3] + bia.w;
        *(float4*)(C + row) = v;
    }
}

// ---------------------------------------------------------------------------
// weight precompute (merged): fp32 -> bf16 hi/lo
// ---------------------------------------------------------------------------
__global__ void prep_weights(const float* __restrict__ Whh, const float* __restrict__ Wihr,
                             __nv_bfloat16* __restrict__ w0h, __nv_bfloat16* __restrict__ w0l,
                             __nv_bfloat16* __restrict__ wch, __nv_bfloat16* __restrict__ wcl)
{
    const size_t HH = (size_t)H_ * H_;
    size_t i = (size_t)blockIdx.x * blockDim.x + threadIdx.x;
    if (i < HH) {
        float v = Whh[i];
        __nv_bfloat16 a = __float2bfloat16(v);
        w0h[i] = a;
        w0l[i] = __float2bfloat16(v - __bfloat162float(a));
    } else {
        size_t j = i - HH;
        const size_t per = (size_t)H_ * K2_;
        int lw = (int)(j / per);
        size_t rem = j % per;
        int n = (int)(rem / K2_);
        int k = (int)(rem % K2_);
        float v = (k < H_) ? Wihr[(size_t)lw * HH + (size_t)n * H_ + k]
                           : Whh[(size_t)(lw + 1) * HH + (size_t)n * H_ + (k - H_)];
        __nv_bfloat16 a = __float2bfloat16(v);
        wch[j] = a;
        wcl[j] = __float2bfloat16(v - __bfloat162float(a));
    }
}

// ---------------------------------------------------------------------------
// Persistent wavefront kernel: 256 CTAs = 4 layers x (2 m x 32 n tiles),
// CTA tile 128x64, 256 threads (8 warps, 32x32 warp tiles), 2 CTAs per SM.
// bf16x3 split mma.sync, 2-stage mbarrier producer/consumer pipeline.
// Two co-resident CTAs per SM give each SMSP two INDEPENDENT instruction
// streams -- when one CTA stalls on a stage wait, the other keeps the
// HMMA pipe busy.
// ---------------------------------------------------------------------------
__device__ __forceinline__ void grid_barrier(unsigned target) {
    __threadfence();
    __syncthreads();
    if (threadIdx.x == 0) {
        atomicAdd(&g_bar, 1u);
        while (*((volatile unsigned*)&g_bar) < target) { }
        __threadfence();
    }
    __syncthreads();
}

__global__ __launch_bounds__(WTHREADS, 2)
void wave_kernel(const float* __restrict__ XP0, const float* __restrict__ b_ihr)
{
    extern __shared__ __nv_bfloat16 sm[];
    __shared__ __align__(8) unsigned long long s_mbar[2 * NSTAGE];  // full[2], empty[2]

    const int tid  = threadIdx.x;
    const int warp = tid >> 5, lane = tid & 31;
    const int l  = blockIdx.x >> 6;          // 64 CTAs per layer
    const int rr = blockIdx.x & 63;
    const int bm = (rr & 1) * 128;           // 2 m-tiles
    const int bn = (rr >> 1) * 64;           // 32 n-tiles

    const unsigned mb = sptr(&s_mbar[0]);
    if (tid == 0) {
        #pragma unroll
        for (int s = 0; s < NSTAGE; s++) {
            mbar_init(mb + s * 8, WTHREADS);                 // full[s]
            mbar_init(mb + (NSTAGE + s) * 8, WTHREADS);      // empty[s]
        }
    }
    __syncthreads();

    const int Kl = (l == 0) ? H_ : K2_;
    const __nv_bfloat16* WBh = (l == 0) ? (g_W0h + (size_t)bn * H_)
                                        : (g_Wch + ((size_t)(l - 1) * H_ + bn) * K2_);
    const __nv_bfloat16* WBl = (l == 0) ? (g_W0l + (size_t)bn * H_)
                                        : (g_Wcl + ((size_t)(l - 1) * H_ + bn) * K2_);

    const int wm = (warp & 3) * 32;      // 4 m sub-tiles of 32
    const int wn = (warp >> 2) * 32;     // 2 n sub-tiles of 32
    const int a_row = lane & 15;
    const int a_k   = (lane >> 4) * 8;
    const int b_row = (lane & 7) + ((lane >> 4) << 3);
    const int b_k   = ((lane >> 3) & 1) * 8;
    const int ldrow = tid >> 3;          // 0..31
    const int ldc   = (tid & 7) * 8;     // elems

    // pipeline state (uniform across CTA; persists across wavefront steps)
    unsigned pf = 0, pe = 0;             // parity bits, one per stage
    unsigned gf = 0, gc = 0;             // monotonic fill / compute counters

    for (int s = 0; s < T_ + L_ - 1; ++s) {
        const int t = s - l;
        const bool act = (t >= 0 && t < T_);
        const int kEnd = act ? ((l == 0) ? (t == 0 ? 0 : H_) : (t == 0 ? H_ : K2_)) : 0;

        if (act) {
            float acc[2][4][4];
            #pragma unroll
            for (int i = 0; i < 2; i++)
                #pragma unroll
                for (int j = 0; j < 4; j++)
                    #pragma unroll
                    for (int q = 0; q < 4; q++) acc[i][j][q] = 0.f;

            auto fill = [&](int k0) {
                const int st = (int)(gf & 1u);
                if (gf >= NSTAGE) {                     // stage reuse: wait consumers
                    mbar_wait(mb + (NSTAGE + st) * 8, (pe >> st) & 1u);
                    pe ^= 1u << st;
                }
                __nv_bfloat16* base = sm + st * STAGE_E;
                // A planes (128 rows)
                {
                    const __nv_bfloat16 *Ah_g, *Al_g;
                    int ak;
                    if (l == 0) {                       // A = h^0_{t-1}
                        size_t off = (size_t)((t - 1) & 1) * BH_;
                        Ah_g = g_Hh + off; Al_g = g_Hl + off; ak = k0;
                    } else if (k0 < H_) {               // A = h^{l-1}_t
                        size_t off = (size_t)((l - 1) * 2 + (t & 1)) * BH_;
                        Ah_g = g_Hh + off; Al_g = g_Hl + off; ak = k0;
                    } else {                            // A = h^l_{t-1}
                        size_t off = (size_t)(l * 2 + ((t - 1) & 1)) * BH_;
                        Ah_g = g_Hh + off; Al_g = g_Hl + off; ak = k0 - H_;
                    }
                    #pragma unroll
                    for (int i = 0; i < 4; i++) {
                        int row = ldrow + i * 32;
                        size_t ga = (size_t)(bm + row) * H_ + ak + ldc;
                        int so = row * PITCH + ldc;
                        cp16(base + OFF_AH + so, Ah_g + ga);
                        cp16(base + OFF_AL + so, Al_g + ga);
                    }
                }
                // B planes (64 rows)
                #pragma unroll
                for (int i = 0; i < 2; i++) {
                    int row = ldrow + i * 32;
                    size_t gb = (size_t)row * Kl + k0 + ldc;
                    int so = row * PITCH + ldc;
                    cp16(base + OFF_BH + so, WBh + gb);
                    cp16(base + OFF_BL + so, WBl + gb);
                }
                cp_arrive_noinc(mb + st * 8);           // arrive full[st] on completion
                gf++;
            };

            auto compute = [&](int stg) {
                const __nv_bfloat16* base = sm + stg * STAGE_E;
                #pragma unroll
                for (int kk = 0; kk < 4; kk++) {
                    unsigned ah[2][4], al[2][4], bh[4][2], bl[4][2];
                    #pragma unroll
                    for (int i = 0; i < 2; i++) {
                        const __nv_bfloat16* pa =
                            base + OFF_AH + (wm + i * 16 + a_row) * PITCH + kk * 16 + a_k;
                        ldsm4(ah[i][0], ah[i][1], ah[i][2], ah[i][3], pa);
                        ldsm4(al[i][0], al[i][1], al[i][2], al[i][3], pa + A_PLANE);
                    }
                    #pragma unroll
                    for (int jp = 0; jp < 2; jp++) {
                        const __nv_bfloat16* pb =
                            base + OFF_BH + (wn + jp * 16 + b_row) * PITCH + kk * 16 + b_k;
                        unsigned r0, r1, r2, r3;
                        ldsm4(r0, r1, r2, r3, pb);
                        bh[jp * 2][0] = r0; bh[jp * 2][1] = r1;
                        bh[jp * 2 + 1][0] = r2; bh[jp * 2 + 1][1] = r3;
                        ldsm4(r0, r1, r2, r3, pb + B_PLANE);
                        bl[jp * 2][0] = r0; bl[jp * 2][1] = r1;
                        bl[jp * 2 + 1][0] = r2; bl[jp * 2 + 1][1] = r3;
                    }
                    #pragma unroll
                    for (int i = 0; i < 2; i++)
                        #pragma unroll
                        for (int j = 0; j < 4; j++) {
                            mma16816(acc[i][j], ah[i], bh[j]);
                            mma16816(acc[i][j], ah[i], bl[j]);
                            mma16816(acc[i][j], al[i], bh[j]);
                        }
                }
            };

            if (kEnd > 0) {
                const int NC = kEnd / CHUNK;          // 32 or 64
                fill(0);
                fill(CHUNK);
                for (int c = 0; c < NC; ++c) {
                    const int sc = (int)(gc & 1u);
                    mbar_wait(mb + sc * 8, (pf >> sc) & 1u);   // wait full[sc]
                    pf ^= 1u << sc;
                    compute(sc);
                    mbar_arrive(mb + (NSTAGE + sc) * 8);       // arrive empty[sc]
                    gc++;
                    if (c + 2 < NC) fill((c + 2) * CHUNK);     // overlaps next compute
                }
            }

            // ---- epilogue: acc + add -> tanh -> bf16 hi/lo split store ----
            {
                const size_t hoff = (size_t)(l * 2 + (t & 1)) * BH_;
                #pragma unroll
                for (int i = 0; i < 2; i++) {
                    const int m0 = bm + wm + i * 16 + (lane >> 2);
                    #pragma unroll
                    for (int j = 0; j < 4; j++) {
                        const int n0 = bn + wn + j * 8 + (lane & 3) * 2;
                        float a0, a1, a2, a3;
                        if (l == 0) {
                            const float* xp = XP0 + (size_t)t * BH_;
                            float2 u = *(const float2*)(xp + (size_t)m0 * H_ + n0);
                            float2 w = *(const float2*)(xp + (size_t)(m0 + 8) * H_ + n0);
                            a0 = u.x; a1 = u.y; a2 = w.x; a3 = w.y;
                        } else {
                            float2 u = *(const float2*)(b_ihr + (size_t)(l - 1) * H_ + n0);
                            a0 = u.x; a1 = u.y; a2 = u.x; a3 = u.y;
                        }
                        float v0 = tanhf(acc[i][j][0] + a0);
                        float v1 = tanhf(acc[i][j][1] + a1);
                        float v2 = tanhf(acc[i][j][2] + a2);
                        float v3 = tanhf(acc[i][j][3] + a3);

                        __nv_bfloat16 h0 = __float2bfloat16(v0), h1 = __float2bfloat16(v1);
                        __nv_bfloat16 h2 = __float2bfloat16(v2), h3 = __float2bfloat16(v3);
                        __nv_bfloat162 ph, pl;
                        ph.x = h0; ph.y = h1;
                        pl.x = __float2bfloat16(v0 - __bfloat162float(h0));
                        pl.y = __float2bfloat16(v1 - __bfloat162float(h1));
                        *(__nv_bfloat162*)(g_Hh + hoff + (size_t)m0 * H_ + n0) = ph;
                        *(__nv_bfloat162*)(g_Hl + hoff + (size_t)m0 * H_ + n0) = pl;
                        ph.x = h2; ph.y = h3;
                        pl.x = __float2bfloat16(v2 - __bfloat162float(h2));
                        pl.y = __float2bfloat16(v3 - __bfloat162float(h3));
                        *(__nv_bfloat162*)(g_Hh + hoff + (size_t)(m0 + 8) * H_ + n0) = ph;
                        *(__nv_bfloat162*)(g_Hl + hoff + (size_t)(m0 + 8) * H_ + n0) = pl;
                    }
                }
            }
        }

        grid_barrier((unsigned)(s + 1) * NCTA);
    }
}

// ---------------------------------------------------------------------------
// Final FC: out[b] = (hi+lo)[b,:] @ W_fc^T + b_fc
// ---------------------------------------------------------------------------
__global__ void fc_kernel(const __nv_bfloat16* __restrict__ hh,
                          const __nv_bfloat16* __restrict__ hl,
                          const float* __restrict__ w, const float* __restrict__ bfc,
                          float* __restrict__ out) {
    __shared__ float red[256];
    const size_t base = (size_t)blockIdx.x * H_;
    float s = 0.f;
    for (int j = threadIdx.x; j < H_; j += 256) {
        float hv = __bfloat162float(hh[base + j]) + __bfloat162float(hl[base + j]);
        s = fmaf(hv, w[j], s);
    }
    red[threadIdx.x] = s;
    __syncthreads();
    for (int off = 128; off; off >>= 1) {
        if (threadIdx.x < off) red[threadIdx.x] += red[threadIdx.x + off];
        __syncthreads();
    }
    if (threadIdx.x == 0) out[blockIdx.x] = red[0] + bfc[0];
}

// ---------------------------------------------------------------------------
extern "C" void kernel_launch(void* const* d_in, const int* in_sizes, int n_in,
                              void* d_out, int out_size)
{
    const float* x      = (const float*)d_in[0];
    const float* W_ih0  = (const float*)d_in[1];
    const float* b_ih0  = (const float*)d_in[2];
    const float* W_ihr  = (const float*)d_in[3];
    const float* b_ihr  = (const float*)d_in[4];
    const float* W_hh   = (const float*)d_in[5];
    const float* W_fc   = (const float*)d_in[6];
    const float* b_fc   = (const float*)d_in[7];
    float* out = (float*)d_out;

    float *XT, *XP;
    __nv_bfloat16 *W0h, *W0l, *Wch, *Wcl, *Hh, *Hl;
    unsigned* bar;
    cudaGetSymbolAddress((void**)&XT,  g_XT);
    cudaGetSymbolAddress((void**)&XP,  g_XP);
    cudaGetSymbolAddress((void**)&W0h, g_W0h);
    cudaGetSymbolAddress((void**)&W0l, g_W0l);
    cudaGetSymbolAddress((void**)&Wch, g_Wch);
    cudaGetSymbolAddress((void**)&Wcl, g_Wcl);
    cudaGetSymbolAddress((void**)&Hh,  g_Hh);
    cudaGetSymbolAddress((void**)&Hl,  g_Hl);
    cudaGetSymbolAddress((void**)&bar, g_bar);

    static int smem_set = 0;
    if (!smem_set) {
        cudaFuncSetAttribute(wave_kernel, cudaFuncAttributeMaxDynamicSharedMemorySize,
                             DYN_SMEM);
        smem_set = 1;
    }

    cudaMemsetAsync(bar, 0, sizeof(unsigned));

    transpose_x<<<(T_ * B_ * (I_ / 4)) / 256, 256>>>(x, XT);

    // layer-0 input projection (fp32, K=64): XP = XT @ W_ih0^T + b_ih0
    gemm_nt<128, 64, 16, 8, 4><<<dim3(H_ / 64, (T_ * B_) / 128), 256>>>(
        XT, W_ih0, b_ih0, XP, T_ * B_, H_, I_);

    // merged weight hi/lo split
    {
        const size_t total = (size_t)H_ * H_ + (size_t)3 * H_ * K2_;
        prep_weights<<<(unsigned)(total / 256), 256>>>(W_hh, W_ihr, W0h, W0l, Wch, Wcl);
    }

    // wavefront over all layers/time (2 CTAs per SM)
    wave_kernel<<<NCTA, WTHREADS, DYN_SMEM>>>(XP, b_ihr);

    // final FC from h^{L-1}_{T-1} (parity (T-1)&1 = 1)
    fc_kernel<<<B_, 256>>>(Hh + (size_t)(3 * 2 + 1) * BH_,
                           Hl + (size_t)(3 * 2 + 1) * BH_, W_fc, b_fc, out);
}

// round 12
// speedup vs baseline: 1.0085x; 1.0085x over previous
#include <cuda_runtime.h>
#include <cuda_bf16.h>
#include <math.h>
#include <stdint.h>

#define B_  256
#define T_  256
#define I_  64
#define H_  2048
#define L_  4
#define BH_ (B_ * H_)
#define K2_ 4096

// ---- wave kernel tiling: CTA tile 128x128, K chunk 64 (bf16), 3 stages ----
#define CHUNK    64
#define PITCH    72                      // bf16 elems per smem row (144B)
#define TILE_E   (128 * PITCH)           // one operand plane (elems)
#define STAGE_E  (4 * TILE_E)            // Ah, Al, Bh, Bl planes
#define NSTAGE   3
#define DYN_SMEM (NSTAGE * STAGE_E * 2)  // 221184 bytes
#define WTHREADS 512

// ---- device scratch (allocation-free contract) ----
__device__ float g_XT[(size_t)T_ * B_ * I_];
__device__ float g_XP[(size_t)T_ * B_ * H_];                 // layer-0 input projection
__device__ __nv_bfloat16 g_W0h[(size_t)H_ * H_];
__device__ __nv_bfloat16 g_W0l[(size_t)H_ * H_];
__device__ __nv_bfloat16 g_Wch[(size_t)3 * H_ * K2_];        // [Wih ; Whh] concat, layers 1..3
__device__ __nv_bfloat16 g_Wcl[(size_t)3 * H_ * K2_];
__device__ __nv_bfloat16 g_Hh[(size_t)L_ * 2 * BH_];         // h ping-pong, hi digit
__device__ __nv_bfloat16 g_Hl[(size_t)L_ * 2 * BH_];         // lo digit
__device__ unsigned g_bar;

// ---------------------------------------------------------------------------
// helpers
// ---------------------------------------------------------------------------
__device__ __forceinline__ unsigned sptr(const void* p) {
    return (unsigned)__cvta_generic_to_shared(p);
}
__device__ __forceinline__ void cp16(__nv_bfloat16* s, const __nv_bfloat16* g) {
    asm volatile("cp.async.cg.shared.global [%0], [%1], 16;" :: "r"(sptr(s)), "l"(g));
}
__device__ __forceinline__ void ldsm4(unsigned& r0, unsigned& r1, unsigned& r2,
                                      unsigned& r3, const __nv_bfloat16* p) {
    asm volatile("ldmatrix.sync.aligned.m8n8.x4.shared.b16 {%0,%1,%2,%3}, [%4];"
                 : "=r"(r0), "=r"(r1), "=r"(r2), "=r"(r3) : "r"(sptr(p)));
}
__device__ __forceinline__ void mma16816(float* d, const unsigned* a, const unsigned* b) {
    asm volatile("mma.sync.aligned.m16n8k16.row.col.f32.bf16.bf16.f32 "
                 "{%0,%1,%2,%3}, {%4,%5,%6,%7}, {%8,%9}, {%0,%1,%2,%3};"
                 : "+f"(d[0]), "+f"(d[1]), "+f"(d[2]), "+f"(d[3])
                 : "r"(a[0]), "r"(a[1]), "r"(a[2]), "r"(a[3]), "r"(b[0]), "r"(b[1]));
}
__device__ __forceinline__ void mbar_init(unsigned mbar, unsigned cnt) {
    asm volatile("mbarrier.init.shared.b64 [%0], %1;" :: "r"(mbar), "r"(cnt) : "memory");
}
__device__ __forceinline__ void mbar_arrive(unsigned mbar) {
    asm volatile("mbarrier.arrive.shared.b64 _, [%0];" :: "r"(mbar) : "memory");
}
__device__ __forceinline__ void cp_arrive_noinc(unsigned mbar) {
    asm volatile("cp.async.mbarrier.arrive.noinc.shared.b64 [%0];" :: "r"(mbar) : "memory");
}
__device__ __forceinline__ void mbar_wait(unsigned mbar, unsigned phase) {
    asm volatile(
        "{\n\t.reg .pred P1;\n\t"
        "WAIT_LOOP_%=:\n\t"
        "mbarrier.try_wait.parity.shared.b64 P1, [%0], %1;\n\t"
        "@P1 bra.uni WAIT_DONE_%=;\n\t"
        "bra.uni WAIT_LOOP_%=;\n\t"
        "WAIT_DONE_%=:\n\t}"
        :: "r"(mbar), "r"(phase) : "memory");
}

// ---------------------------------------------------------------------------
// x[B,T,I] -> XT[T,B,I]
// ---------------------------------------------------------------------------
__global__ void transpose_x(const float* __restrict__ x, float* __restrict__ xt) {
    int idx = blockIdx.x * blockDim.x + threadIdx.x;
    int i4 = idx & 15;
    int b  = (idx >> 4) & (B_ - 1);
    int t  = idx >> 12;
    float4 v = *(const float4*)(x + ((size_t)b * T_ + t) * I_ + i4 * 4);
    *(float4*)(xt + ((size_t)t * B_ + b) * I_ + i4 * 4) = v;
}

// ---------------------------------------------------------------------------
// fp32 NT GEMM (layer-0 input projection, K=64): C = A@W^T + bias
// ---------------------------------------------------------------------------
template<int BM, int BN, int BK, int TM, int TN>
__global__ __launch_bounds__((BM / TM) * (BN / TN))
void gemm_nt(const float* __restrict__ A, const float* __restrict__ W,
             const float* __restrict__ bias, float* __restrict__ C,
             int M, int N, int K)
{
    constexpr int NT  = (BM / TM) * (BN / TN);
    constexpr int KV  = BK / 4;
    constexpr int AV  = (BM * BK) / (NT * 4);
    constexpr int BV  = (BN * BK) / (NT * 4);
    constexpr int ARS = NT / KV;

    __shared__ __align__(16) float As[BK][BM + 4];
    __shared__ __align__(16) float Bs[BK][BN + 4];

    const int tid = threadIdx.x;
    const int bm  = blockIdx.y * BM;
    const int bn  = blockIdx.x * BN;
    const int lr = tid / KV;
    const int lc = (tid % KV) * 4;
    const float* Ag = A + (size_t)(bm + lr) * K + lc;
    const float* Wg = W + (size_t)(bn + lr) * K + lc;
    const int tx = tid % (BN / TN);
    const int ty = tid / (BN / TN);

    float acc[TM][TN];
    #pragma unroll
    for (int i = 0; i < TM; i++)
        #pragma unroll
        for (int j = 0; j < TN; j++) acc[i][j] = 0.f;

    float4 ra[AV], rb[BV];
    #pragma unroll
    for (int v = 0; v < AV; v++) ra[v] = *(const float4*)(Ag + (size_t)v * ARS * K);
    #pragma unroll
    for (int v = 0; v < BV; v++) rb[v] = *(const float4*)(Wg + (size_t)v * ARS * K);

    for (int k0 = 0; k0 < K; k0 += BK) {
        __syncthreads();
        #pragma unroll
        for (int v = 0; v < AV; v++) {
            As[lc + 0][lr + v * ARS] = ra[v].x; As[lc + 1][lr + v * ARS] = ra[v].y;
            As[lc + 2][lr + v * ARS] = ra[v].z; As[lc + 3][lr + v * ARS] = ra[v].w;
        }
        #pragma unroll
        for (int v = 0; v < BV; v++) {
            Bs[lc + 0][lr + v * ARS] = rb[v].x; Bs[lc + 1][lr + v * ARS] = rb[v].y;
            Bs[lc + 2][lr + v * ARS] = rb[v].z; Bs[lc + 3][lr + v * ARS] = rb[v].w;
        }
        __syncthreads();
        if (k0 + BK < K) {
            #pragma unroll
            for (int v = 0; v < AV; v++) ra[v] = *(const float4*)(Ag + (size_t)v * ARS * K + k0 + BK);
            #pragma unroll
            for (int v = 0; v < BV; v++) rb[v] = *(const float4*)(Wg + (size_t)v * ARS * K + k0 + BK);
        }
        #pragma unroll
        for (int kk = 0; kk < BK; ++kk) {
            float a[TM], b[TN];
            #pragma unroll
            for (int i = 0; i < TM; i += 4) *(float4*)&a[i] = *(const float4*)&As[kk][ty * TM + i];
            #pragma unroll
            for (int j = 0; j < TN; j += 4) *(float4*)&b[j] = *(const float4*)&Bs[kk][tx * TN + j];
            #pragma unroll
            for (int i = 0; i < TM; i++)
                #pragma unroll
                for (int j = 0; j < TN; j++) acc[i][j] = fmaf(a[i], b[j], acc[i][j]);
        }
    }
    const int n0 = bn + tx * TN;
    float4 bia = *(const float4*)(bias + n0);
    #pragma unroll
    for (int i = 0; i < TM; i++) {
        const size_t row = (size_t)(bm + ty * TM + i) * N + n0;
        float4 v;
        v.x = acc[i][0] + bia.x; v.y = acc[i][1] + bia.y;
        v.z = acc[i][2] + bia.z; v.w = acc[i][3] + bia.w;
        *(float4*)(C + row) = v;
    }
}

// ---------------------------------------------------------------------------
// weight precompute (merged): fp32 -> bf16 hi/lo
// ---------------------------------------------------------------------------
__global__ void prep_weights(const float* __restrict__ Whh, const float* __restrict__ Wihr,
                             __nv_bfloat16* __restrict__ w0h, __nv_bfloat16* __restrict__ w0l,
                             __nv_bfloat16* __restrict__ wch, __nv_bfloat16* __restrict__ wcl)
{
    const size_t HH = (size_t)H_ * H_;
    size_t i = (size_t)blockIdx.x * blockDim.x + threadIdx.x;
    if (i < HH) {
        float v = Whh[i];
        __nv_bfloat16 a = __float2bfloat16(v);
        w0h[i] = a;
        w0l[i] = __float2bfloat16(v - __bfloat162float(a));
    } else {
        size_t j = i - HH;
        const size_t per = (size_t)H_ * K2_;
        int lw = (int)(j / per);
        size_t rem = j % per;
        int n = (int)(rem / K2_);
        int k = (int)(rem % K2_);
        float v = (k < H_) ? Wihr[(size_t)lw * HH + (size_t)n * H_ + k]
                           : Whh[(size_t)(lw + 1) * HH + (size_t)n * H_ + (k - H_)];
        __nv_bfloat16 a = __float2bfloat16(v);
        wch[j] = a;
        wcl[j] = __float2bfloat16(v - __bfloat162float(a));
    }
}

// ---------------------------------------------------------------------------
// Persistent wavefront kernel: 128 CTAs = 4 layers x (2 m x 16 n tiles),
// CTA tile 128x128, 512 threads (16 warps, 32x32 warp tiles), bf16x3 split
// mma.sync, 3-stage mbarrier producer/consumer pipeline.
// MMA issue order is PASS-MAJOR: all 8 independent accumulators per pass,
// so each acc register is revisited only after 8 intervening HMMAs --
// breaks the 3-deep accumulator RAW chains of the previous revisions.
// ---------------------------------------------------------------------------
__device__ __forceinline__ void grid_barrier(unsigned target) {
    __threadfence();
    __syncthreads();
    if (threadIdx.x == 0) {
        atomicAdd(&g_bar, 1u);
        while (*((volatile unsigned*)&g_bar) < target) { }
        __threadfence();
    }
    __syncthreads();
}

__global__ __launch_bounds__(WTHREADS, 1)
void wave_kernel(const float* __restrict__ XP0, const float* __restrict__ b_ihr)
{
    extern __shared__ __nv_bfloat16 sm[];
    __shared__ __align__(8) unsigned long long s_mbar[2 * NSTAGE];  // full[3], empty[3]

    const int tid  = threadIdx.x;
    const int warp = tid >> 5, lane = tid & 31;
    const int l  = blockIdx.x >> 5;
    const int rr = blockIdx.x & 31;
    const int bm = (rr & 1) * 128;
    const int bn = (rr >> 1) * 128;

    const unsigned mb = sptr(&s_mbar[0]);
    if (tid == 0) {
        #pragma unroll
        for (int s = 0; s < NSTAGE; s++) {
            mbar_init(mb + s * 8, WTHREADS);                 // full[s]
            mbar_init(mb + (NSTAGE + s) * 8, WTHREADS);      // empty[s]
        }
    }
    __syncthreads();

    const int Kl = (l == 0) ? H_ : K2_;
    const __nv_bfloat16* WBh = (l == 0) ? (g_W0h + (size_t)bn * H_)
                                        : (g_Wch + (size_t)(l - 1) * H_ * K2_ + (size_t)bn * K2_);
    const __nv_bfloat16* WBl = (l == 0) ? (g_W0l + (size_t)bn * H_)
                                        : (g_Wcl + (size_t)(l - 1) * H_ * K2_ + (size_t)bn * K2_);

    const int wm = (warp & 3) * 32;      // 4 m sub-tiles of 32
    const int wn = (warp >> 2) * 32;     // 4 n sub-tiles of 32
    const int a_row = lane & 15;
    const int a_k   = (lane >> 4) * 8;
    const int b_row = (lane & 7) + ((lane >> 4) << 3);
    const int b_k   = ((lane >> 3) & 1) * 8;
    const int ldrow = tid >> 3;          // 0..63
    const int ldc   = (tid & 7) * 8;     // elems

    // pipeline state (uniform across CTA; persists across wavefront steps)
    unsigned pf = 0, pe = 0;             // parity bits, one per stage
    unsigned gf = 0, gc = 0;             // monotonic fill / compute counters

    for (int s = 0; s < T_ + L_ - 1; ++s) {
        const int t = s - l;
        const bool act = (t >= 0 && t < T_);
        const int kEnd = act ? ((l == 0) ? (t == 0 ? 0 : H_) : (t == 0 ? H_ : K2_)) : 0;

        if (act) {
            float acc[2][4][4];
            #pragma unroll
            for (int i = 0; i < 2; i++)
                #pragma unroll
                for (int j = 0; j < 4; j++)
                    #pragma unroll
                    for (int q = 0; q < 4; q++) acc[i][j][q] = 0.f;

            auto fill = [&](int k0) {
                const int st = (int)(gf % NSTAGE);
                if (gf >= NSTAGE) {                     // stage reuse: wait consumers
                    mbar_wait(mb + (NSTAGE + st) * 8, (pe >> st) & 1u);
                    pe ^= 1u << st;
                }
                __nv_bfloat16* base = sm + st * STAGE_E;
                // A planes
                {
                    const __nv_bfloat16 *Ah_g, *Al_g;
                    int ak;
                    if (l == 0) {                       // A = h^0_{t-1}
                        size_t off = (size_t)((t - 1) & 1) * BH_;
                        Ah_g = g_Hh + off; Al_g = g_Hl + off; ak = k0;
                    } else if (k0 < H_) {               // A = h^{l-1}_t
                        size_t off = (size_t)((l - 1) * 2 + (t & 1)) * BH_;
                        Ah_g = g_Hh + off; Al_g = g_Hl + off; ak = k0;
                    } else {                            // A = h^l_{t-1}
                        size_t off = (size_t)(l * 2 + ((t - 1) & 1)) * BH_;
                        Ah_g = g_Hh + off; Al_g = g_Hl + off; ak = k0 - H_;
                    }
                    #pragma unroll
                    for (int i = 0; i < 2; i++) {
                        int row = ldrow + i * 64;
                        size_t ga = (size_t)(bm + row) * H_ + ak + ldc;
                        int so = row * PITCH + ldc;
                        cp16(base + so,          Ah_g + ga);
                        cp16(base + TILE_E + so, Al_g + ga);
                    }
                }
                // B planes
                #pragma unroll
                for (int i = 0; i < 2; i++) {
                    int row = ldrow + i * 64;
                    size_t gb = (size_t)row * Kl + k0 + ldc;
                    int so = row * PITCH + ldc;
                    cp16(base + 2 * TILE_E + so, WBh + gb);
                    cp16(base + 3 * TILE_E + so, WBl + gb);
                }
                cp_arrive_noinc(mb + st * 8);           // arrive full[st] on completion
                gf++;
            };

            auto compute = [&](int stg) {
                const __nv_bfloat16* base = sm + stg * STAGE_E;
                #pragma unroll
                for (int kk = 0; kk < 4; kk++) {
                    unsigned ah[2][4], al[2][4], bh[4][2], bl[4][2];
                    #pragma unroll
                    for (int i = 0; i < 2; i++) {
                        const __nv_bfloat16* pa =
                            base + (wm + i * 16 + a_row) * PITCH + kk * 16 + a_k;
                        ldsm4(ah[i][0], ah[i][1], ah[i][2], ah[i][3], pa);
                        ldsm4(al[i][0], al[i][1], al[i][2], al[i][3], pa + TILE_E);
                    }
                    #pragma unroll
                    for (int jp = 0; jp < 2; jp++) {
                        const __nv_bfloat16* pb =
                            base + 2 * TILE_E + (wn + jp * 16 + b_row) * PITCH + kk * 16 + b_k;
                        unsigned r0, r1, r2, r3;
                        ldsm4(r0, r1, r2, r3, pb);
                        bh[jp * 2][0] = r0; bh[jp * 2][1] = r1;
                        bh[jp * 2 + 1][0] = r2; bh[jp * 2 + 1][1] = r3;
                        ldsm4(r0, r1, r2, r3, pb + TILE_E);
                        bl[jp * 2][0] = r0; bl[jp * 2][1] = r1;
                        bl[jp * 2 + 1][0] = r2; bl[jp * 2 + 1][1] = r3;
                    }
                    // PASS-MAJOR issue order: each pass touches 8 DISTINCT
                    // accumulators; a given acc[i][j] is revisited only after
                    // 8 intervening independent HMMAs (covers HMMA latency).
                    // Per-element accumulation order is unchanged (hh, hl, lh)
                    // so results are bit-identical to the pass-minor order.
                    #pragma unroll
                    for (int i = 0; i < 2; i++)
                        #pragma unroll
                        for (int j = 0; j < 4; j++)
                            mma16816(acc[i][j], ah[i], bh[j]);
                    #pragma unroll
                    for (int i = 0; i < 2; i++)
                        #pragma unroll
                        for (int j = 0; j < 4; j++)
                            mma16816(acc[i][j], ah[i], bl[j]);
                    #pragma unroll
                    for (int i = 0; i < 2; i++)
                        #pragma unroll
                        for (int j = 0; j < 4; j++)
                            mma16816(acc[i][j], al[i], bh[j]);
                }
            };

            if (kEnd > 0) {
                const int NC = kEnd / CHUNK;          // 32 or 64
                fill(0);
                fill(CHUNK);
                for (int c = 0; c < NC; ++c) {
                    const int sc = (int)(gc % NSTAGE);
                    mbar_wait(mb + sc * 8, (pf >> sc) & 1u);   // wait full[sc]
                    pf ^= 1u << sc;
                    if (c + 2 < NC) fill((c + 2) * CHUNK);     // overlaps compute below
                    compute(sc);
                    mbar_arrive(mb + (NSTAGE + sc) * 8);       // arrive empty[sc]
                    gc++;
                }
            }

            // ---- epilogue: acc + add -> tanh -> bf16 hi/lo split store ----
            {
                const size_t hoff = (size_t)(l * 2 + (t & 1)) * BH_;
                #pragma unroll
                for (int i = 0; i < 2; i++) {
                    const int m0 = bm + wm + i * 16 + (lane >> 2);
                    #pragma unroll
                    for (int j = 0; j < 4; j++) {
                        const int n0 = bn + wn + j * 8 + (lane & 3) * 2;
                        float a0, a1, a2, a3;
                        if (l == 0) {
                            const float* xp = XP0 + (size_t)t * BH_;
                            float2 u = *(const float2*)(xp + (size_t)m0 * H_ + n0);
                            float2 w = *(const float2*)(xp + (size_t)(m0 + 8) * H_ + n0);
                            a0 = u.x; a1 = u.y; a2 = w.x; a3 = w.y;
                        } else {
                            float2 u = *(const float2*)(b_ihr + (size_t)(l - 1) * H_ + n0);
                            a0 = u.x; a1 = u.y; a2 = u.x; a3 = u.y;
                        }
                        float v0 = tanhf(acc[i][j][0] + a0);
                        float v1 = tanhf(acc[i][j][1] + a1);
                        float v2 = tanhf(acc[i][j][2] + a2);
                        float v3 = tanhf(acc[i][j][3] + a3);

                        __nv_bfloat16 h0 = __float2bfloat16(v0), h1 = __float2bfloat16(v1);
                        __nv_bfloat16 h2 = __float2bfloat16(v2), h3 = __float2bfloat16(v3);
                        __nv_bfloat162 ph, pl;
                        ph.x = h0; ph.y = h1;
                        pl.x = __float2bfloat16(v0 - __bfloat162float(h0));
                        pl.y = __float2bfloat16(v1 - __bfloat162float(h1));
                        *(__nv_bfloat162*)(g_Hh + hoff + (size_t)m0 * H_ + n0) = ph;
                        *(__nv_bfloat162*)(g_Hl + hoff + (size_t)m0 * H_ + n0) = pl;
                        ph.x = h2; ph.y = h3;
                        pl.x = __float2bfloat16(v2 - __bfloat162float(h2));
                        pl.y = __float2bfloat16(v3 - __bfloat162float(h3));
                        *(__nv_bfloat162*)(g_Hh + hoff + (size_t)(m0 + 8) * H_ + n0) = ph;
                        *(__nv_bfloat162*)(g_Hl + hoff + (size_t)(m0 + 8) * H_ + n0) = pl;
                    }
                }
            }
        }

        grid_barrier((unsigned)(s + 1) * 128u);
    }
}

// ---------------------------------------------------------------------------
// Final FC: out[b] = (hi+lo)[b,:] @ W_fc^T + b_fc
// ---------------------------------------------------------------------------
__global__ void fc_kernel(const __nv_bfloat16* __restrict__ hh,
                          const __nv_bfloat16* __restrict__ hl,
                          const float* __restrict__ w, const float* __restrict__ bfc,
                          float* __restrict__ out) {
    __shared__ float red[256];
    const size_t base = (size_t)blockIdx.x * H_;
    float s = 0.f;
    for (int j = threadIdx.x; j < H_; j += 256) {
        float hv = __bfloat162float(hh[base + j]) + __bfloat162float(hl[base + j]);
        s = fmaf(hv, w[j], s);
    }
    red[threadIdx.x] = s;
    __syncthreads();
    for (int off = 128; off; off >>= 1) {
        if (threadIdx.x < off) red[threadIdx.x] += red[threadIdx.x + off];
        __syncthreads();
    }
    if (threadIdx.x == 0) out[blockIdx.x] = red[0] + bfc[0];
}

// ---------------------------------------------------------------------------
extern "C" void kernel_launch(void* const* d_in, const int* in_sizes, int n_in,
                              void* d_out, int out_size)
{
    const float* x      = (const float*)d_in[0];
    const float* W_ih0  = (const float*)d_in[1];
    const float* b_ih0  = (const float*)d_in[2];
    const float* W_ihr  = (const float*)d_in[3];
    const float* b_ihr  = (const float*)d_in[4];
    const float* W_hh   = (const float*)d_in[5];
    const float* W_fc   = (const float*)d_in[6];
    const float* b_fc   = (const float*)d_in[7];
    float* out = (float*)d_out;

    float *XT, *XP;
    __nv_bfloat16 *W0h, *W0l, *Wch, *Wcl, *Hh, *Hl;
    unsigned* bar;
    cudaGetSymbolAddress((void**)&XT,  g_XT);
    cudaGetSymbolAddress((void**)&XP,  g_XP);
    cudaGetSymbolAddress((void**)&W0h, g_W0h);
    cudaGetSymbolAddress((void**)&W0l, g_W0l);
    cudaGetSymbolAddress((void**)&Wch, g_Wch);
    cudaGetSymbolAddress((void**)&Wcl, g_Wcl);
    cudaGetSymbolAddress((void**)&Hh,  g_Hh);
    cudaGetSymbolAddress((void**)&Hl,  g_Hl);
    cudaGetSymbolAddress((void**)&bar, g_bar);

    static int smem_set = 0;
    if (!smem_set) {
        cudaFuncSetAttribute(wave_kernel, cudaFuncAttributeMaxDynamicSharedMemorySize,
                             DYN_SMEM);
        smem_set = 1;
    }

    cudaMemsetAsync(bar, 0, sizeof(unsigned));

    transpose_x<<<(T_ * B_ * (I_ / 4)) / 256, 256>>>(x, XT);

    // layer-0 input projection (fp32, K=64): XP = XT @ W_ih0^T + b_ih0
    gemm_nt<128, 64, 16, 8, 4><<<dim3(H_ / 64, (T_ * B_) / 128), 256>>>(
        XT, W_ih0, b_ih0, XP, T_ * B_, H_, I_);

    // merged weight hi/lo split
    {
        const size_t total = (size_t)H_ * H_ + (size_t)3 * H_ * K2_;
        prep_weights<<<(unsigned)(total / 256), 256>>>(W_hh, W_ihr, W0h, W0l, Wch, Wcl);
    }

    // wavefront over all layers/time
    wave_kernel<<<128, WTHREADS, DYN_SMEM>>>(XP, b_ihr);

    // final FC from h^{L-1}_{T-1} (parity (T-1)&1 = 1)
    fc_kernel<<<B_, 256>>>(Hh + (size_t)(3 * 2 + 1) * BH_,
                           Hl + (size_t)(3 * 2 + 1) * BH_, W_fc, b_fc, out);
}

// round 13
// speedup vs baseline: 1.0178x; 1.0092x over previous
#include <cuda_runtime.h>
#include <cuda_fp16.h>
#include <math.h>
#include <stdint.h>

#define B_  256
#define T_  256
#define I_  64
#define H_  2048
#define L_  4
#define BH_ (B_ * H_)
#define K2_ 4096

// ---- wave kernel tiling: CTA tile 128x128, K chunk 64 (fp16), 3 stages ----
#define CHUNK    64
#define PITCH    72                      // fp16 elems per smem row (144B)
#define TILE_E   (128 * PITCH)           // one operand plane (elems)
#define STAGE_E  (4 * TILE_E)            // Ah, Al, Bh, Bl planes
#define NSTAGE   3
#define DYN_SMEM (NSTAGE * STAGE_E * 2)  // 221184 bytes
#define WTHREADS 512
#define RSCALE   1024.f                  // residual digit scale (2^10)
#define INV_RS   (1.f / 1024.f)

// ---- device scratch (allocation-free contract) ----
__device__ float g_XT[(size_t)T_ * B_ * I_];
__device__ float g_XP[(size_t)T_ * B_ * H_];                 // layer-0 input projection
__device__ __half g_W0h[(size_t)H_ * H_];
__device__ __half g_W0l[(size_t)H_ * H_];
__device__ __half g_Wch[(size_t)3 * H_ * K2_];               // [Wih ; Whh] concat, layers 1..3
__device__ __half g_Wcl[(size_t)3 * H_ * K2_];
__device__ __half g_Hh[(size_t)L_ * 2 * BH_];                // h ping-pong, hi digit
__device__ __half g_Hl[(size_t)L_ * 2 * BH_];                // lo digit (x1024)
__device__ unsigned g_bar;

// ---------------------------------------------------------------------------
// helpers
// ---------------------------------------------------------------------------
__device__ __forceinline__ unsigned sptr(const void* p) {
    return (unsigned)__cvta_generic_to_shared(p);
}
__device__ __forceinline__ void cp16(__half* s, const __half* g) {
    asm volatile("cp.async.cg.shared.global [%0], [%1], 16;" :: "r"(sptr(s)), "l"(g));
}
__device__ __forceinline__ void ldsm4(unsigned& r0, unsigned& r1, unsigned& r2,
                                      unsigned& r3, const __half* p) {
    asm volatile("ldmatrix.sync.aligned.m8n8.x4.shared.b16 {%0,%1,%2,%3}, [%4];"
                 : "=r"(r0), "=r"(r1), "=r"(r2), "=r"(r3) : "r"(sptr(p)));
}
// fp16 inputs, fp32 accumulate (hi*hi pass)
__device__ __forceinline__ void mma_f32acc(float* d, const unsigned* a, const unsigned* b) {
    asm volatile("mma.sync.aligned.m16n8k16.row.col.f32.f16.f16.f32 "
                 "{%0,%1,%2,%3}, {%4,%5,%6,%7}, {%8,%9}, {%0,%1,%2,%3};"
                 : "+f"(d[0]), "+f"(d[1]), "+f"(d[2]), "+f"(d[3])
                 : "r"(a[0]), "r"(a[1]), "r"(a[2]), "r"(a[3]), "r"(b[0]), "r"(b[1]));
}
// fp16 inputs, fp16 accumulate (correction passes)
__device__ __forceinline__ void mma_f16acc(unsigned* d, const unsigned* a, const unsigned* b) {
    asm volatile("mma.sync.aligned.m16n8k16.row.col.f16.f16.f16.f16 "
                 "{%0,%1}, {%2,%3,%4,%5}, {%6,%7}, {%0,%1};"
                 : "+r"(d[0]), "+r"(d[1])
                 : "r"(a[0]), "r"(a[1]), "r"(a[2]), "r"(a[3]), "r"(b[0]), "r"(b[1]));
}
__device__ __forceinline__ void mbar_init(unsigned mbar, unsigned cnt) {
    asm volatile("mbarrier.init.shared.b64 [%0], %1;" :: "r"(mbar), "r"(cnt) : "memory");
}
__device__ __forceinline__ void mbar_arrive(unsigned mbar) {
    asm volatile("mbarrier.arrive.shared.b64 _, [%0];" :: "r"(mbar) : "memory");
}
__device__ __forceinline__ void cp_arrive_noinc(unsigned mbar) {
    asm volatile("cp.async.mbarrier.arrive.noinc.shared.b64 [%0];" :: "r"(mbar) : "memory");
}
__device__ __forceinline__ void mbar_wait(unsigned mbar, unsigned phase) {
    asm volatile(
        "{\n\t.reg .pred P1;\n\t"
        "WAIT_LOOP_%=:\n\t"
        "mbarrier.try_wait.parity.shared.b64 P1, [%0], %1;\n\t"
        "@P1 bra.uni WAIT_DONE_%=;\n\t"
        "bra.uni WAIT_LOOP_%=;\n\t"
        "WAIT_DONE_%=:\n\t}"
        :: "r"(mbar), "r"(phase) : "memory");
}

// ---------------------------------------------------------------------------
// x[B,T,I] -> XT[T,B,I]
// ---------------------------------------------------------------------------
__global__ void transpose_x(const float* __restrict__ x, float* __restrict__ xt) {
    int idx = blockIdx.x * blockDim.x + threadIdx.x;
    int i4 = idx & 15;
    int b  = (idx >> 4) & (B_ - 1);
    int t  = idx >> 12;
    float4 v = *(const float4*)(x + ((size_t)b * T_ + t) * I_ + i4 * 4);
    *(float4*)(xt + ((size_t)t * B_ + b) * I_ + i4 * 4) = v;
}

// ---------------------------------------------------------------------------
// fp32 NT GEMM (layer-0 input projection, K=64): C = A@W^T + bias
// ---------------------------------------------------------------------------
template<int BM, int BN, int BK, int TM, int TN>
__global__ __launch_bounds__((BM / TM) * (BN / TN))
void gemm_nt(const float* __restrict__ A, const float* __restrict__ W,
             const float* __restrict__ bias, float* __restrict__ C,
             int M, int N, int K)
{
    constexpr int NT  = (BM / TM) * (BN / TN);
    constexpr int KV  = BK / 4;
    constexpr int AV  = (BM * BK) / (NT * 4);
    constexpr int BV  = (BN * BK) / (NT * 4);
    constexpr int ARS = NT / KV;

    __shared__ __align__(16) float As[BK][BM + 4];
    __shared__ __align__(16) float Bs[BK][BN + 4];

    const int tid = threadIdx.x;
    const int bm  = blockIdx.y * BM;
    const int bn  = blockIdx.x * BN;
    const int lr = tid / KV;
    const int lc = (tid % KV) * 4;
    const float* Ag = A + (size_t)(bm + lr) * K + lc;
    const float* Wg = W + (size_t)(bn + lr) * K + lc;
    const int tx = tid % (BN / TN);
    const int ty = tid / (BN / TN);

    float acc[TM][TN];
    #pragma unroll
    for (int i = 0; i < TM; i++)
        #pragma unroll
        for (int j = 0; j < TN; j++) acc[i][j] = 0.f;

    float4 ra[AV], rb[BV];
    #pragma unroll
    for (int v = 0; v < AV; v++) ra[v] = *(const float4*)(Ag + (size_t)v * ARS * K);
    #pragma unroll
    for (int v = 0; v < BV; v++) rb[v] = *(const float4*)(Wg + (size_t)v * ARS * K);

    for (int k0 = 0; k0 < K; k0 += BK) {
        __syncthreads();
        #pragma unroll
        for (int v = 0; v < AV; v++) {
            As[lc + 0][lr + v * ARS] = ra[v].x; As[lc + 1][lr + v * ARS] = ra[v].y;
            As[lc + 2][lr + v * ARS] = ra[v].z; As[lc + 3][lr + v * ARS] = ra[v].w;
        }
        #pragma unroll
        for (int v = 0; v < BV; v++) {
            Bs[lc + 0][lr + v * ARS] = rb[v].x; Bs[lc + 1][lr + v * ARS] = rb[v].y;
            Bs[lc + 2][lr + v * ARS] = rb[v].z; Bs[lc + 3][lr + v * ARS] = rb[v].w;
        }
        __syncthreads();
        if (k0 + BK < K) {
            #pragma unroll
            for (int v = 0; v < AV; v++) ra[v] = *(const float4*)(Ag + (size_t)v * ARS * K + k0 + BK);
            #pragma unroll
            for (int v = 0; v < BV; v++) rb[v] = *(const float4*)(Wg + (size_t)v * ARS * K + k0 + BK);
        }
        #pragma unroll
        for (int kk = 0; kk < BK; ++kk) {
            float a[TM], b[TN];
            #pragma unroll
            for (int i = 0; i < TM; i += 4) *(float4*)&a[i] = *(const float4*)&As[kk][ty * TM + i];
            #pragma unroll
            for (int j = 0; j < TN; j += 4) *(float4*)&b[j] = *(const float4*)&Bs[kk][tx * TN + j];
            #pragma unroll
            for (int i = 0; i < TM; i++)
                #pragma unroll
                for (int j = 0; j < TN; j++) acc[i][j] = fmaf(a[i], b[j], acc[i][j]);
        }
    }
    const int n0 = bn + tx * TN;
    float4 bia = *(const float4*)(bias + n0);
    #pragma unroll
    for (int i = 0; i < TM; i++) {
        const size_t row = (size_t)(bm + ty * TM + i) * N + n0;
        float4 v;
        v.x = acc[i][0] + bia.x; v.y = acc[i][1] + bia.y;
        v.z = acc[i][2] + bia.z; v.w = acc[i][3] + bia.w;
        *(float4*)(C + row) = v;
    }
}

// ---------------------------------------------------------------------------
// weight precompute (merged): fp32 -> fp16 hi + scaled fp16 lo
// ---------------------------------------------------------------------------
__global__ void prep_weights(const float* __restrict__ Whh, const float* __restrict__ Wihr,
                             __half* __restrict__ w0h, __half* __restrict__ w0l,
                             __half* __restrict__ wch, __half* __restrict__ wcl)
{
    const size_t HH = (size_t)H_ * H_;
    size_t i = (size_t)blockIdx.x * blockDim.x + threadIdx.x;
    if (i < HH) {
        float v = Whh[i];
        __half a = __float2half(v);
        w0h[i] = a;
        w0l[i] = __float2half((v - __half2float(a)) * RSCALE);
    } else {
        size_t j = i - HH;
        const size_t per = (size_t)H_ * K2_;
        int lw = (int)(j / per);
        size_t rem = j % per;
        int n = (int)(rem / K2_);
        int k = (int)(rem % K2_);
        float v = (k < H_) ? Wihr[(size_t)lw * HH + (size_t)n * H_ + k]
                           : Whh[(size_t)(lw + 1) * HH + (size_t)n * H_ + (k - H_)];
        __half a = __float2half(v);
        wch[j] = a;
        wcl[j] = __float2half((v - __half2float(a)) * RSCALE);
    }
}

// ---------------------------------------------------------------------------
// Persistent wavefront kernel: 128 CTAs = 4 layers x (2 m x 16 n tiles),
// CTA tile 128x128, 512 threads (16 warps, 32x32 warp tiles), fp16 2-digit
// split: hi*hi in FP32-ACCUM HMMA, both corrections (hi*lo + lo*hi, residuals
// pre-scaled by 2^10) in FP16-ACCUM HMMA sharing one accumulator set.
// Tests the "fp32-accum HMMA is half-rate on sm_103a" hypothesis.
// 3-stage mbarrier producer/consumer pipeline.
// ---------------------------------------------------------------------------
__device__ __forceinline__ void grid_barrier(unsigned target) {
    __threadfence();
    __syncthreads();
    if (threadIdx.x == 0) {
        atomicAdd(&g_bar, 1u);
        while (*((volatile unsigned*)&g_bar) < target) { }
        __threadfence();
    }
    __syncthreads();
}

__global__ __launch_bounds__(WTHREADS, 1)
void wave_kernel(const float* __restrict__ XP0, const float* __restrict__ b_ihr)
{
    extern __shared__ __half sm[];
    __shared__ __align__(8) unsigned long long s_mbar[2 * NSTAGE];  // full[3], empty[3]

    const int tid  = threadIdx.x;
    const int warp = tid >> 5, lane = tid & 31;
    const int l  = blockIdx.x >> 5;
    const int rr = blockIdx.x & 31;
    const int bm = (rr & 1) * 128;
    const int bn = (rr >> 1) * 128;

    const unsigned mb = sptr(&s_mbar[0]);
    if (tid == 0) {
        #pragma unroll
        for (int s = 0; s < NSTAGE; s++) {
            mbar_init(mb + s * 8, WTHREADS);                 // full[s]
            mbar_init(mb + (NSTAGE + s) * 8, WTHREADS);      // empty[s]
        }
    }
    __syncthreads();

    const int Kl = (l == 0) ? H_ : K2_;
    const __half* WBh = (l == 0) ? (g_W0h + (size_t)bn * H_)
                                 : (g_Wch + (size_t)(l - 1) * H_ * K2_ + (size_t)bn * K2_);
    const __half* WBl = (l == 0) ? (g_W0l + (size_t)bn * H_)
                                 : (g_Wcl + (size_t)(l - 1) * H_ * K2_ + (size_t)bn * K2_);

    const int wm = (warp & 3) * 32;      // 4 m sub-tiles of 32
    const int wn = (warp >> 2) * 32;     // 4 n sub-tiles of 32
    const int a_row = lane & 15;
    const int a_k   = (lane >> 4) * 8;
    const int b_row = (lane & 7) + ((lane >> 4) << 3);
    const int b_k   = ((lane >> 3) & 1) * 8;
    const int ldrow = tid >> 3;          // 0..63
    const int ldc   = (tid & 7) * 8;     // elems

    // pipeline state (uniform across CTA; persists across wavefront steps)
    unsigned pf = 0, pe = 0;             // parity bits, one per stage
    unsigned gf = 0, gc = 0;             // monotonic fill / compute counters

    for (int s = 0; s < T_ + L_ - 1; ++s) {
        const int t = s - l;
        const bool act = (t >= 0 && t < T_);
        const int kEnd = act ? ((l == 0) ? (t == 0 ? 0 : H_) : (t == 0 ? H_ : K2_)) : 0;

        if (act) {
            float acch[2][4][4];         // hi*hi, fp32 accum
            unsigned accc[2][4][2];      // corrections, fp16 accum (half2 x2)
            #pragma unroll
            for (int i = 0; i < 2; i++)
                #pragma unroll
                for (int j = 0; j < 4; j++) {
                    #pragma unroll
                    for (int q = 0; q < 4; q++) acch[i][j][q] = 0.f;
                    accc[i][j][0] = 0u; accc[i][j][1] = 0u;
                }

            auto fill = [&](int k0) {
                const int st = (int)(gf % NSTAGE);
                if (gf >= NSTAGE) {                     // stage reuse: wait consumers
                    mbar_wait(mb + (NSTAGE + st) * 8, (pe >> st) & 1u);
                    pe ^= 1u << st;
                }
                __half* base = sm + st * STAGE_E;
                // A planes
                {
                    const __half *Ah_g, *Al_g;
                    int ak;
                    if (l == 0) {                       // A = h^0_{t-1}
                        size_t off = (size_t)((t - 1) & 1) * BH_;
                        Ah_g = g_Hh + off; Al_g = g_Hl + off; ak = k0;
                    } else if (k0 < H_) {               // A = h^{l-1}_t
                        size_t off = (size_t)((l - 1) * 2 + (t & 1)) * BH_;
                        Ah_g = g_Hh + off; Al_g = g_Hl + off; ak = k0;
                    } else {                            // A = h^l_{t-1}
                        size_t off = (size_t)(l * 2 + ((t - 1) & 1)) * BH_;
                        Ah_g = g_Hh + off; Al_g = g_Hl + off; ak = k0 - H_;
                    }
                    #pragma unroll
                    for (int i = 0; i < 2; i++) {
                        int row = ldrow + i * 64;
                        size_t ga = (size_t)(bm + row) * H_ + ak + ldc;
                        int so = row * PITCH + ldc;
                        cp16(base + so,          Ah_g + ga);
                        cp16(base + TILE_E + so, Al_g + ga);
                    }
                }
                // B planes
                #pragma unroll
                for (int i = 0; i < 2; i++) {
                    int row = ldrow + i * 64;
                    size_t gb = (size_t)row * Kl + k0 + ldc;
                    int so = row * PITCH + ldc;
                    cp16(base + 2 * TILE_E + so, WBh + gb);
                    cp16(base + 3 * TILE_E + so, WBl + gb);
                }
                cp_arrive_noinc(mb + st * 8);           // arrive full[st] on completion
                gf++;
            };

            auto compute = [&](int stg) {
                const __half* base = sm + stg * STAGE_E;
                #pragma unroll
                for (int kk = 0; kk < 4; kk++) {
                    unsigned ah[2][4], al[2][4], bh[4][2], bl[4][2];
                    #pragma unroll
                    for (int i = 0; i < 2; i++) {
                        const __half* pa =
                            base + (wm + i * 16 + a_row) * PITCH + kk * 16 + a_k;
                        ldsm4(ah[i][0], ah[i][1], ah[i][2], ah[i][3], pa);
                        ldsm4(al[i][0], al[i][1], al[i][2], al[i][3], pa + TILE_E);
                    }
                    #pragma unroll
                    for (int jp = 0; jp < 2; jp++) {
                        const __half* pb =
                            base + 2 * TILE_E + (wn + jp * 16 + b_row) * PITCH + kk * 16 + b_k;
                        unsigned r0, r1, r2, r3;
                        ldsm4(r0, r1, r2, r3, pb);
                        bh[jp * 2][0] = r0; bh[jp * 2][1] = r1;
                        bh[jp * 2 + 1][0] = r2; bh[jp * 2 + 1][1] = r3;
                        ldsm4(r0, r1, r2, r3, pb + TILE_E);
                        bl[jp * 2][0] = r0; bl[jp * 2][1] = r1;
                        bl[jp * 2 + 1][0] = r2; bl[jp * 2 + 1][1] = r3;
                    }
                    #pragma unroll
                    for (int i = 0; i < 2; i++)
                        #pragma unroll
                        for (int j = 0; j < 4; j++) {
                            mma_f32acc(acch[i][j], ah[i], bh[j]);   // hi*hi
                            mma_f16acc(accc[i][j], ah[i], bl[j]);   // hi*lo'
                            mma_f16acc(accc[i][j], al[i], bh[j]);   // lo'*hi
                        }
                }
            };

            if (kEnd > 0) {
                const int NC = kEnd / CHUNK;          // 32 or 64
                fill(0);
                fill(CHUNK);
                for (int c = 0; c < NC; ++c) {
                    const int sc = (int)(gc % NSTAGE);
                    mbar_wait(mb + sc * 8, (pf >> sc) & 1u);   // wait full[sc]
                    pf ^= 1u << sc;
                    if (c + 2 < NC) fill((c + 2) * CHUNK);     // overlaps compute below
                    compute(sc);
                    mbar_arrive(mb + (NSTAGE + sc) * 8);       // arrive empty[sc]
                    gc++;
                }
            }

            // ---- epilogue: hh + corr/1024 + add -> tanh -> fp16 digit store ----
            {
                const size_t hoff = (size_t)(l * 2 + (t & 1)) * BH_;
                #pragma unroll
                for (int i = 0; i < 2; i++) {
                    const int m0 = bm + wm + i * 16 + (lane >> 2);
                    #pragma unroll
                    for (int j = 0; j < 4; j++) {
                        const int n0 = bn + wn + j * 8 + (lane & 3) * 2;
                        float a0, a1, a2, a3;
                        if (l == 0) {
                            const float* xp = XP0 + (size_t)t * BH_;
                            float2 u = *(const float2*)(xp + (size_t)m0 * H_ + n0);
                            float2 w = *(const float2*)(xp + (size_t)(m0 + 8) * H_ + n0);
                            a0 = u.x; a1 = u.y; a2 = w.x; a3 = w.y;
                        } else {
                            float2 u = *(const float2*)(b_ihr + (size_t)(l - 1) * H_ + n0);
                            a0 = u.x; a1 = u.y; a2 = u.x; a3 = u.y;
                        }
                        __half2 c01 = *(__half2*)&accc[i][j][0];
                        __half2 c23 = *(__half2*)&accc[i][j][1];
                        float v0 = tanhf(acch[i][j][0] + __half2float(c01.x) * INV_RS + a0);
                        float v1 = tanhf(acch[i][j][1] + __half2float(c01.y) * INV_RS + a1);
                        float v2 = tanhf(acch[i][j][2] + __half2float(c23.x) * INV_RS + a2);
                        float v3 = tanhf(acch[i][j][3] + __half2float(c23.y) * INV_RS + a3);

                        __half h0 = __float2half(v0), h1 = __float2half(v1);
                        __half h2 = __float2half(v2), h3 = __float2half(v3);
                        __half2 ph, pl;
                        ph.x = h0; ph.y = h1;
                        pl.x = __float2half((v0 - __half2float(h0)) * RSCALE);
                        pl.y = __float2half((v1 - __half2float(h1)) * RSCALE);
                        *(__half2*)(g_Hh + hoff + (size_t)m0 * H_ + n0) = ph;
                        *(__half2*)(g_Hl + hoff + (size_t)m0 * H_ + n0) = pl;
                        ph.x = h2; ph.y = h3;
                        pl.x = __float2half((v2 - __half2float(h2)) * RSCALE);
                        pl.y = __float2half((v3 - __half2float(h3)) * RSCALE);
                        *(__half2*)(g_Hh + hoff + (size_t)(m0 + 8) * H_ + n0) = ph;
                        *(__half2*)(g_Hl + hoff + (size_t)(m0 + 8) * H_ + n0) = pl;
                    }
                }
            }
        }

        grid_barrier((unsigned)(s + 1) * 128u);
    }
}

// ---------------------------------------------------------------------------
// Final FC: out[b] = (hi + lo/1024)[b,:] @ W_fc^T + b_fc
// ---------------------------------------------------------------------------
__global__ void fc_kernel(const __half* __restrict__ hh,
                          const __half* __restrict__ hl,
                          const float* __restrict__ w, const float* __restrict__ bfc,
                          float* __restrict__ out) {
    __shared__ float red[256];
    const size_t base = (size_t)blockIdx.x * H_;
    float s = 0.f;
    for (int j = threadIdx.x; j < H_; j += 256) {
        float hv = __half2float(hh[base + j]) + __half2float(hl[base + j]) * INV_RS;
        s = fmaf(hv, w[j], s);
    }
    red[threadIdx.x] = s;
    __syncthreads();
    for (int off = 128; off; off >>= 1) {
        if (threadIdx.x < off) red[threadIdx.x] += red[threadIdx.x + off];
        __syncthreads();
    }
    if (threadIdx.x == 0) out[blockIdx.x] = red[0] + bfc[0];
}

// ---------------------------------------------------------------------------
extern "C" void kernel_launch(void* const* d_in, const int* in_sizes, int n_in,
                              void* d_out, int out_size)
{
    const float* x      = (const float*)d_in[0];
    const float* W_ih0  = (const float*)d_in[1];
    const float* b_ih0  = (const float*)d_in[2];
    const float* W_ihr  = (const float*)d_in[3];
    const float* b_ihr  = (const float*)d_in[4];
    const float* W_hh   = (const float*)d_in[5];
    const float* W_fc   = (const float*)d_in[6];
    const float* b_fc   = (const float*)d_in[7];
    float* out = (float*)d_out;

    float *XT, *XP;
    __half *W0h, *W0l, *Wch, *Wcl, *Hh, *Hl;
    unsigned* bar;
    cudaGetSymbolAddress((void**)&XT,  g_XT);
    cudaGetSymbolAddress((void**)&XP,  g_XP);
    cudaGetSymbolAddress((void**)&W0h, g_W0h);
    cudaGetSymbolAddress((void**)&W0l, g_W0l);
    cudaGetSymbolAddress((void**)&Wch, g_Wch);
    cudaGetSymbolAddress((void**)&Wcl, g_Wcl);
    cudaGetSymbolAddress((void**)&Hh,  g_Hh);
    cudaGetSymbolAddress((void**)&Hl,  g_Hl);
    cudaGetSymbolAddress((void**)&bar, g_bar);

    static int smem_set = 0;
    if (!smem_set) {
        cudaFuncSetAttribute(wave_kernel, cudaFuncAttributeMaxDynamicSharedMemorySize,
                             DYN_SMEM);
        smem_set = 1;
    }

    cudaMemsetAsync(bar, 0, sizeof(unsigned));

    transpose_x<<<(T_ * B_ * (I_ / 4)) / 256, 256>>>(x, XT);

    // layer-0 input projection (fp32, K=64): XP = XT @ W_ih0^T + b_ih0
    gemm_nt<128, 64, 16, 8, 4><<<dim3(H_ / 64, (T_ * B_) / 128), 256>>>(
        XT, W_ih0, b_ih0, XP, T_ * B_, H_, I_);

    // merged weight hi/lo split (fp16 digits)
    {
        const size_t total = (size_t)H_ * H_ + (size_t)3 * H_ * K2_;
        prep_weights<<<(unsigned)(total / 256), 256>>>(W_hh, W_ihr, W0h, W0l, Wch, Wcl);
    }

    // wavefront over all layers/time
    wave_kernel<<<128, WTHREADS, DYN_SMEM>>>(XP, b_ihr);

    // final FC from h^{L-1}_{T-1} (parity (T-1)&1 = 1)
    fc_kernel<<<B_, 256>>>(Hh + (size_t)(3 * 2 + 1) * BH_,
                           Hl + (size_t)(3 * 2 + 1) * BH_, W_fc, b_fc, out);
}

// round 14
// speedup vs baseline: 1.0335x; 1.0154x over previous
#include <cuda_runtime.h>
#include <cuda_fp16.h>
#include <math.h>
#include <stdint.h>

#define B_  256
#define T_  256
#define I_  64
#define H_  2048
#define L_  4
#define BH_ (B_ * H_)
#define K2_ 4096

// ---- wave kernel tiling: CTA tile 128x128, K chunk 64 (fp16), 3 stages ----
#define CHUNK    64
#define PITCH    72                      // fp16 elems per smem row (144B)
#define TILE_E   (128 * PITCH)           // one operand plane (elems)
#define STAGE_E  (4 * TILE_E)            // Ah, Al, Bh, Bl planes
#define NSTAGE   3
#define DYN_SMEM (NSTAGE * STAGE_E * 2)  // 221184 bytes
#define WTHREADS 512
#define RSCALE   1024.f                  // residual digit scale (2^10)
#define INV_RS   (1.f / 1024.f)

// ---- device scratch (allocation-free contract) ----
__device__ float g_XT[(size_t)T_ * B_ * I_];
__device__ float g_XP[(size_t)T_ * B_ * H_];                 // layer-0 input projection
__device__ __half g_W0h[(size_t)H_ * H_];
__device__ __half g_W0l[(size_t)H_ * H_];
__device__ __half g_Wch[(size_t)3 * H_ * K2_];               // [Wih ; Whh] concat, layers 1..3
__device__ __half g_Wcl[(size_t)3 * H_ * K2_];
__device__ __half g_Hh[(size_t)L_ * 2 * BH_];                // h ping-pong, hi digit
__device__ __half g_Hl[(size_t)L_ * 2 * BH_];                // lo digit (x1024)
__device__ unsigned g_bar;

// ---------------------------------------------------------------------------
// helpers
// ---------------------------------------------------------------------------
__device__ __forceinline__ unsigned sptr(const void* p) {
    return (unsigned)__cvta_generic_to_shared(p);
}
__device__ __forceinline__ void cp16(__half* s, const __half* g) {
    asm volatile("cp.async.cg.shared.global [%0], [%1], 16;" :: "r"(sptr(s)), "l"(g));
}
__device__ __forceinline__ void ldsm4(unsigned& r0, unsigned& r1, unsigned& r2,
                                      unsigned& r3, const __half* p) {
    asm volatile("ldmatrix.sync.aligned.m8n8.x4.shared.b16 {%0,%1,%2,%3}, [%4];"
                 : "=r"(r0), "=r"(r1), "=r"(r2), "=r"(r3) : "r"(sptr(p)));
}
// fp16 inputs, fp32 accumulate (hi*hi pass)
__device__ __forceinline__ void mma_f32acc(float* d, const unsigned* a, const unsigned* b) {
    asm volatile("mma.sync.aligned.m16n8k16.row.col.f32.f16.f16.f32 "
                 "{%0,%1,%2,%3}, {%4,%5,%6,%7}, {%8,%9}, {%0,%1,%2,%3};"
                 : "+f"(d[0]), "+f"(d[1]), "+f"(d[2]), "+f"(d[3])
                 : "r"(a[0]), "r"(a[1]), "r"(a[2]), "r"(a[3]), "r"(b[0]), "r"(b[1]));
}
// fp16 inputs, fp16 accumulate (correction passes)
__device__ __forceinline__ void mma_f16acc(unsigned* d, const unsigned* a, const unsigned* b) {
    asm volatile("mma.sync.aligned.m16n8k16.row.col.f16.f16.f16.f16 "
                 "{%0,%1}, {%2,%3,%4,%5}, {%6,%7}, {%0,%1};"
                 : "+r"(d[0]), "+r"(d[1])
                 : "r"(a[0]), "r"(a[1]), "r"(a[2]), "r"(a[3]), "r"(b[0]), "r"(b[1]));
}
__device__ __forceinline__ void mbar_init(unsigned mbar, unsigned cnt) {
    asm volatile("mbarrier.init.shared.b64 [%0], %1;" :: "r"(mbar), "r"(cnt) : "memory");
}
__device__ __forceinline__ void mbar_arrive(unsigned mbar) {
    asm volatile("mbarrier.arrive.shared.b64 _, [%0];" :: "r"(mbar) : "memory");
}
__device__ __forceinline__ void cp_arrive_noinc(unsigned mbar) {
    asm volatile("cp.async.mbarrier.arrive.noinc.shared.b64 [%0];" :: "r"(mbar) : "memory");
}
__device__ __forceinline__ void mbar_wait(unsigned mbar, unsigned phase) {
    asm volatile(
        "{\n\t.reg .pred P1;\n\t"
        "WAIT_LOOP_%=:\n\t"
        "mbarrier.try_wait.parity.shared.b64 P1, [%0], %1;\n\t"
        "@P1 bra.uni WAIT_DONE_%=;\n\t"
        "bra.uni WAIT_LOOP_%=;\n\t"
        "WAIT_DONE_%=:\n\t}"
        :: "r"(mbar), "r"(phase) : "memory");
}

// ---------------------------------------------------------------------------
// x[B,T,I] -> XT[T,B,I]
// ---------------------------------------------------------------------------
__global__ void transpose_x(const float* __restrict__ x, float* __restrict__ xt) {
    int idx = blockIdx.x * blockDim.x + threadIdx.x;
    int i4 = idx & 15;
    int b  = (idx >> 4) & (B_ - 1);
    int t  = idx >> 12;
    float4 v = *(const float4*)(x + ((size_t)b * T_ + t) * I_ + i4 * 4);
    *(float4*)(xt + ((size_t)t * B_ + b) * I_ + i4 * 4) = v;
}

// ---------------------------------------------------------------------------
// fp32 NT GEMM (layer-0 input projection, K=64): C = A@W^T + bias
// ---------------------------------------------------------------------------
template<int BM, int BN, int BK, int TM, int TN>
__global__ __launch_bounds__((BM / TM) * (BN / TN))
void gemm_nt(const float* __restrict__ A, const float* __restrict__ W,
             const float* __restrict__ bias, float* __restrict__ C,
             int M, int N, int K)
{
    constexpr int NT  = (BM / TM) * (BN / TN);
    constexpr int KV  = BK / 4;
    constexpr int AV  = (BM * BK) / (NT * 4);
    constexpr int BV  = (BN * BK) / (NT * 4);
    constexpr int ARS = NT / KV;

    __shared__ __align__(16) float As[BK][BM + 4];
    __shared__ __align__(16) float Bs[BK][BN + 4];

    const int tid = threadIdx.x;
    const int bm  = blockIdx.y * BM;
    const int bn  = blockIdx.x * BN;
    const int lr = tid / KV;
    const int lc = (tid % KV) * 4;
    const float* Ag = A + (size_t)(bm + lr) * K + lc;
    const float* Wg = W + (size_t)(bn + lr) * K + lc;
    const int tx = tid % (BN / TN);
    const int ty = tid / (BN / TN);

    float acc[TM][TN];
    #pragma unroll
    for (int i = 0; i < TM; i++)
        #pragma unroll
        for (int j = 0; j < TN; j++) acc[i][j] = 0.f;

    float4 ra[AV], rb[BV];
    #pragma unroll
    for (int v = 0; v < AV; v++) ra[v] = *(const float4*)(Ag + (size_t)v * ARS * K);
    #pragma unroll
    for (int v = 0; v < BV; v++) rb[v] = *(const float4*)(Wg + (size_t)v * ARS * K);

    for (int k0 = 0; k0 < K; k0 += BK) {
        __syncthreads();
        #pragma unroll
        for (int v = 0; v < AV; v++) {
            As[lc + 0][lr + v * ARS] = ra[v].x; As[lc + 1][lr + v * ARS] = ra[v].y;
            As[lc + 2][lr + v * ARS] = ra[v].z; As[lc + 3][lr + v * ARS] = ra[v].w;
        }
        #pragma unroll
        for (int v = 0; v < BV; v++) {
            Bs[lc + 0][lr + v * ARS] = rb[v].x; Bs[lc + 1][lr + v * ARS] = rb[v].y;
            Bs[lc + 2][lr + v * ARS] = rb[v].z; Bs[lc + 3][lr + v * ARS] = rb[v].w;
        }
        __syncthreads();
        if (k0 + BK < K) {
            #pragma unroll
            for (int v = 0; v < AV; v++) ra[v] = *(const float4*)(Ag + (size_t)v * ARS * K + k0 + BK);
            #pragma unroll
            for (int v = 0; v < BV; v++) rb[v] = *(const float4*)(Wg + (size_t)v * ARS * K + k0 + BK);
        }
        #pragma unroll
        for (int kk = 0; kk < BK; ++kk) {
            float a[TM], b[TN];
            #pragma unroll
            for (int i = 0; i < TM; i += 4) *(float4*)&a[i] = *(const float4*)&As[kk][ty * TM + i];
            #pragma unroll
            for (int j = 0; j < TN; j += 4) *(float4*)&b[j] = *(const float4*)&Bs[kk][tx * TN + j];
            #pragma unroll
            for (int i = 0; i < TM; i++)
                #pragma unroll
                for (int j = 0; j < TN; j++) acc[i][j] = fmaf(a[i], b[j], acc[i][j]);
        }
    }
    const int n0 = bn + tx * TN;
    float4 bia = *(const float4*)(bias + n0);
    #pragma unroll
    for (int i = 0; i < TM; i++) {
        const size_t row = (size_t)(bm + ty * TM + i) * N + n0;
        float4 v;
        v.x = acc[i][0] + bia.x; v.y = acc[i][1] + bia.y;
        v.z = acc[i][2] + bia.z; v.w = acc[i][3] + bia.w;
        *(float4*)(C + row) = v;
    }
}

// ---------------------------------------------------------------------------
// weight precompute (merged): fp32 -> fp16 hi + scaled fp16 lo
// ---------------------------------------------------------------------------
__global__ void prep_weights(const float* __restrict__ Whh, const float* __restrict__ Wihr,
                             __half* __restrict__ w0h, __half* __restrict__ w0l,
                             __half* __restrict__ wch, __half* __restrict__ wcl)
{
    const size_t HH = (size_t)H_ * H_;
    size_t i = (size_t)blockIdx.x * blockDim.x + threadIdx.x;
    if (i < HH) {
        float v = Whh[i];
        __half a = __float2half(v);
        w0h[i] = a;
        w0l[i] = __float2half((v - __half2float(a)) * RSCALE);
    } else {
        size_t j = i - HH;
        const size_t per = (size_t)H_ * K2_;
        int lw = (int)(j / per);
        size_t rem = j % per;
        int n = (int)(rem / K2_);
        int k = (int)(rem % K2_);
        float v = (k < H_) ? Wihr[(size_t)lw * HH + (size_t)n * H_ + k]
                           : Whh[(size_t)(lw + 1) * HH + (size_t)n * H_ + (k - H_)];
        __half a = __float2half(v);
        wch[j] = a;
        wcl[j] = __float2half((v - __half2float(a)) * RSCALE);
    }
}

// ---------------------------------------------------------------------------
// Persistent wavefront kernel: 128 CTAs = 4 layers x (2 m x 16 n tiles),
// CTA tile 128x128, 512 threads (16 warps, 32x32 warp tiles), fp16 2-digit
// split (hi*hi fp32-accum, corrections fp16-accum), 3-stage mbarrier pipeline.
// NEW: cross-barrier B prefetch -- B planes are step-invariant per CTA, so
// the next step's first two B-chunk loads are issued BEFORE the grid barrier
// (their L2 round-trip overlaps barrier wait); after the barrier only the A
// planes are issued, and the single cp-arrive covers both (per-thread
// cp.async ordering).
// ---------------------------------------------------------------------------
__device__ __forceinline__ void grid_barrier(unsigned target) {
    __threadfence();
    __syncthreads();
    if (threadIdx.x == 0) {
        atomicAdd(&g_bar, 1u);
        while (*((volatile unsigned*)&g_bar) < target) { }
        __threadfence();
    }
    __syncthreads();
}

__global__ __launch_bounds__(WTHREADS, 1)
void wave_kernel(const float* __restrict__ XP0, const float* __restrict__ b_ihr)
{
    extern __shared__ __half sm[];
    __shared__ __align__(8) unsigned long long s_mbar[2 * NSTAGE];  // full[3], empty[3]

    const int tid  = threadIdx.x;
    const int warp = tid >> 5, lane = tid & 31;
    const int l  = blockIdx.x >> 5;
    const int rr = blockIdx.x & 31;
    const int bm = (rr & 1) * 128;
    const int bn = (rr >> 1) * 128;

    const unsigned mb = sptr(&s_mbar[0]);
    if (tid == 0) {
        #pragma unroll
        for (int s = 0; s < NSTAGE; s++) {
            mbar_init(mb + s * 8, WTHREADS);                 // full[s]
            mbar_init(mb + (NSTAGE + s) * 8, WTHREADS);      // empty[s]
        }
    }
    __syncthreads();

    const int Kl = (l == 0) ? H_ : K2_;
    const __half* WBh = (l == 0) ? (g_W0h + (size_t)bn * H_)
                                 : (g_Wch + (size_t)(l - 1) * H_ * K2_ + (size_t)bn * K2_);
    const __half* WBl = (l == 0) ? (g_W0l + (size_t)bn * H_)
                                 : (g_Wcl + (size_t)(l - 1) * H_ * K2_ + (size_t)bn * K2_);

    const int wm = (warp & 3) * 32;      // 4 m sub-tiles of 32
    const int wn = (warp >> 2) * 32;     // 4 n sub-tiles of 32
    const int a_row = lane & 15;
    const int a_k   = (lane >> 4) * 8;
    const int b_row = (lane & 7) + ((lane >> 4) << 3);
    const int b_k   = ((lane >> 3) & 1) * 8;
    const int ldrow = tid >> 3;          // 0..63
    const int ldc   = (tid & 7) * 8;     // elems

    // pipeline state (uniform across CTA; persists across wavefront steps)
    unsigned pf = 0, pe = 0;             // parity bits, one per stage
    unsigned gf = 0, gc = 0;             // monotonic fill / compute counters
    bool preB = false;                   // B of chunks 0,1 already issued pre-barrier

    // B-plane loader into a resolved stage (step-invariant addresses)
    auto loadB = [&](int st, int k0) {
        __half* base = sm + st * STAGE_E;
        #pragma unroll
        for (int i = 0; i < 2; i++) {
            int row = ldrow + i * 64;
            size_t gb = (size_t)row * Kl + k0 + ldc;
            int so = row * PITCH + ldc;
            cp16(base + 2 * TILE_E + so, WBh + gb);
            cp16(base + 3 * TILE_E + so, WBl + gb);
        }
    };

    for (int s = 0; s < T_ + L_ - 1; ++s) {
        const int t = s - l;
        const bool act = (t >= 0 && t < T_);
        const int kEnd = act ? ((l == 0) ? (t == 0 ? 0 : H_) : (t == 0 ? H_ : K2_)) : 0;

        if (act) {
            float acch[2][4][4];         // hi*hi, fp32 accum
            unsigned accc[2][4][2];      // corrections, fp16 accum (half2 x2)
            #pragma unroll
            for (int i = 0; i < 2; i++)
                #pragma unroll
                for (int j = 0; j < 4; j++) {
                    #pragma unroll
                    for (int q = 0; q < 4; q++) acch[i][j][q] = 0.f;
                    accc[i][j][0] = 0u; accc[i][j][1] = 0u;
                }

            auto loadA = [&](int st, int k0) {
                __half* base = sm + st * STAGE_E;
                const __half *Ah_g, *Al_g;
                int ak;
                if (l == 0) {                       // A = h^0_{t-1}
                    size_t off = (size_t)((t - 1) & 1) * BH_;
                    Ah_g = g_Hh + off; Al_g = g_Hl + off; ak = k0;
                } else if (k0 < H_) {               // A = h^{l-1}_t
                    size_t off = (size_t)((l - 1) * 2 + (t & 1)) * BH_;
                    Ah_g = g_Hh + off; Al_g = g_Hl + off; ak = k0;
                } else {                            // A = h^l_{t-1}
                    size_t off = (size_t)(l * 2 + ((t - 1) & 1)) * BH_;
                    Ah_g = g_Hh + off; Al_g = g_Hl + off; ak = k0 - H_;
                }
                #pragma unroll
                for (int i = 0; i < 2; i++) {
                    int row = ldrow + i * 64;
                    size_t ga = (size_t)(bm + row) * H_ + ak + ldc;
                    int so = row * PITCH + ldc;
                    cp16(base + so,          Ah_g + ga);
                    cp16(base + TILE_E + so, Al_g + ga);
                }
            };

            // full fill (A+B, with empty-wait) for chunks >= 2
            auto fill = [&](int k0) {
                const int st = (int)(gf % NSTAGE);
                if (gf >= NSTAGE) {
                    mbar_wait(mb + (NSTAGE + st) * 8, (pe >> st) & 1u);
                    pe ^= 1u << st;
                }
                loadA(st, k0);
                loadB(st, k0);
                cp_arrive_noinc(mb + st * 8);
                gf++;
            };

            auto compute = [&](int stg) {
                const __half* base = sm + stg * STAGE_E;
                #pragma unroll
                for (int kk = 0; kk < 4; kk++) {
                    unsigned ah[2][4], al[2][4], bh[4][2], bl[4][2];
                    #pragma unroll
                    for (int i = 0; i < 2; i++) {
                        const __half* pa =
                            base + (wm + i * 16 + a_row) * PITCH + kk * 16 + a_k;
                        ldsm4(ah[i][0], ah[i][1], ah[i][2], ah[i][3], pa);
                        ldsm4(al[i][0], al[i][1], al[i][2], al[i][3], pa + TILE_E);
                    }
                    #pragma unroll
                    for (int jp = 0; jp < 2; jp++) {
                        const __half* pb =
                            base + 2 * TILE_E + (wn + jp * 16 + b_row) * PITCH + kk * 16 + b_k;
                        unsigned r0, r1, r2, r3;
                        ldsm4(r0, r1, r2, r3, pb);
                        bh[jp * 2][0] = r0; bh[jp * 2][1] = r1;
                        bh[jp * 2 + 1][0] = r2; bh[jp * 2 + 1][1] = r3;
                        ldsm4(r0, r1, r2, r3, pb + TILE_E);
                        bl[jp * 2][0] = r0; bl[jp * 2][1] = r1;
                        bl[jp * 2 + 1][0] = r2; bl[jp * 2 + 1][1] = r3;
                    }
                    #pragma unroll
                    for (int i = 0; i < 2; i++)
                        #pragma unroll
                        for (int j = 0; j < 4; j++) {
                            mma_f32acc(acch[i][j], ah[i], bh[j]);   // hi*hi
                            mma_f16acc(accc[i][j], ah[i], bl[j]);   // hi*lo'
                            mma_f16acc(accc[i][j], al[i], bh[j]);   // lo'*hi
                        }
                }
            };

            if (kEnd > 0) {
                const int NC = kEnd / CHUNK;          // 32 or 64
                // chunks 0,1: B possibly prefetched pre-barrier (empty-waits done)
                #pragma unroll
                for (int c = 0; c < 2; ++c) {
                    const int st = (int)(gf % NSTAGE);
                    if (!preB) {
                        if (gf >= NSTAGE) {
                            mbar_wait(mb + (NSTAGE + st) * 8, (pe >> st) & 1u);
                            pe ^= 1u << st;
                        }
                        loadB(st, c * CHUNK);
                    }
                    loadA(st, c * CHUNK);
                    cp_arrive_noinc(mb + st * 8);
                    gf++;
                }
                for (int c = 0; c < NC; ++c) {
                    const int sc = (int)(gc % NSTAGE);
                    mbar_wait(mb + sc * 8, (pf >> sc) & 1u);   // wait full[sc]
                    pf ^= 1u << sc;
                    if (c + 2 < NC) fill((c + 2) * CHUNK);     // overlaps compute below
                    compute(sc);
                    mbar_arrive(mb + (NSTAGE + sc) * 8);       // arrive empty[sc]
                    gc++;
                }
            }

            // ---- epilogue: hh + corr/1024 + add -> tanh -> fp16 digit store ----
            {
                const size_t hoff = (size_t)(l * 2 + (t & 1)) * BH_;
                #pragma unroll
                for (int i = 0; i < 2; i++) {
                    const int m0 = bm + wm + i * 16 + (lane >> 2);
                    #pragma unroll
                    for (int j = 0; j < 4; j++) {
                        const int n0 = bn + wn + j * 8 + (lane & 3) * 2;
                        float a0, a1, a2, a3;
                        if (l == 0) {
                            const float* xp = XP0 + (size_t)t * BH_;
                            float2 u = *(const float2*)(xp + (size_t)m0 * H_ + n0);
                            float2 w = *(const float2*)(xp + (size_t)(m0 + 8) * H_ + n0);
                            a0 = u.x; a1 = u.y; a2 = w.x; a3 = w.y;
                        } else {
                            float2 u = *(const float2*)(b_ihr + (size_t)(l - 1) * H_ + n0);
                            a0 = u.x; a1 = u.y; a2 = u.x; a3 = u.y;
                        }
                        __half2 c01 = *(__half2*)&accc[i][j][0];
                        __half2 c23 = *(__half2*)&accc[i][j][1];
                        float v0 = tanhf(acch[i][j][0] + __half2float(c01.x) * INV_RS + a0);
                        float v1 = tanhf(acch[i][j][1] + __half2float(c01.y) * INV_RS + a1);
                        float v2 = tanhf(acch[i][j][2] + __half2float(c23.x) * INV_RS + a2);
                        float v3 = tanhf(acch[i][j][3] + __half2float(c23.y) * INV_RS + a3);

                        __half h0 = __float2half(v0), h1 = __float2half(v1);
                        __half h2 = __float2half(v2), h3 = __float2half(v3);
                        __half2 ph, pl;
                        ph.x = h0; ph.y = h1;
                        pl.x = __float2half((v0 - __half2float(h0)) * RSCALE);
                        pl.y = __float2half((v1 - __half2float(h1)) * RSCALE);
                        *(__half2*)(g_Hh + hoff + (size_t)m0 * H_ + n0) = ph;
                        *(__half2*)(g_Hl + hoff + (size_t)m0 * H_ + n0) = pl;
                        ph.x = h2; ph.y = h3;
                        pl.x = __float2half((v2 - __half2float(h2)) * RSCALE);
                        pl.y = __float2half((v3 - __half2float(h3)) * RSCALE);
                        *(__half2*)(g_Hh + hoff + (size_t)(m0 + 8) * H_ + n0) = ph;
                        *(__half2*)(g_Hl + hoff + (size_t)(m0 + 8) * H_ + n0) = pl;
                    }
                }
            }
        }

        // ---- cross-barrier B prefetch for next step (chunks 0,1) ----
        {
            const int t2 = s + 1 - l;
            const bool act2 = (t2 >= 0 && t2 < T_);
            const int kEnd2 = act2 ? ((l == 0) ? (t2 == 0 ? 0 : H_) : (t2 == 0 ? H_ : K2_)) : 0;
            preB = false;
            if (kEnd2 > 0) {
                #pragma unroll
                for (int c = 0; c < 2; ++c) {
                    const int st = (int)((gf + c) % NSTAGE);
                    if (gf + c >= NSTAGE) {            // consume empty token now
                        mbar_wait(mb + (NSTAGE + st) * 8, (pe >> st) & 1u);
                        pe ^= 1u << st;
                    }
                    loadB(st, c * CHUNK);              // B is step-invariant: safe pre-barrier
                }
                preB = true;
            }
        }

        grid_barrier((unsigned)(s + 1) * 128u);
    }
}

// ---------------------------------------------------------------------------
// Final FC: out[b] = (hi + lo/1024)[b,:] @ W_fc^T + b_fc
// ---------------------------------------------------------------------------
__global__ void fc_kernel(const __half* __restrict__ hh,
                          const __half* __restrict__ hl,
                          const float* __restrict__ w, const float* __restrict__ bfc,
                          float* __restrict__ out) {
    __shared__ float red[256];
    const size_t base = (size_t)blockIdx.x * H_;
    float s = 0.f;
    for (int j = threadIdx.x; j < H_; j += 256) {
        float hv = __half2float(hh[base + j]) + __half2float(hl[base + j]) * INV_RS;
        s = fmaf(hv, w[j], s);
    }
    red[threadIdx.x] = s;
    __syncthreads();
    for (int off = 128; off; off >>= 1) {
        if (threadIdx.x < off) red[threadIdx.x] += red[threadIdx.x + off];
        __syncthreads();
    }
    if (threadIdx.x == 0) out[blockIdx.x] = red[0] + bfc[0];
}

// ---------------------------------------------------------------------------
extern "C" void kernel_launch(void* const* d_in, const int* in_sizes, int n_in,
                              void* d_out, int out_size)
{
    const float* x      = (const float*)d_in[0];
    const float* W_ih0  = (const float*)d_in[1];
    const float* b_ih0  = (const float*)d_in[2];
    const float* W_ihr  = (const float*)d_in[3];
    const float* b_ihr  = (const float*)d_in[4];
    const float* W_hh   = (const float*)d_in[5];
    const float* W_fc   = (const float*)d_in[6];
    const float* b_fc   = (const float*)d_in[7];
    float* out = (float*)d_out;

    float *XT, *XP;
    __half *W0h, *W0l, *Wch, *Wcl, *Hh, *Hl;
    unsigned* bar;
    cudaGetSymbolAddress((void**)&XT,  g_XT);
    cudaGetSymbolAddress((void**)&XP,  g_XP);
    cudaGetSymbolAddress((void**)&W0h, g_W0h);
    cudaGetSymbolAddress((void**)&W0l, g_W0l);
    cudaGetSymbolAddress((void**)&Wch, g_Wch);
    cudaGetSymbolAddress((void**)&Wcl, g_Wcl);
    cudaGetSymbolAddress((void**)&Hh,  g_Hh);
    cudaGetSymbolAddress((void**)&Hl,  g_Hl);
    cudaGetSymbolAddress((void**)&bar, g_bar);

    static int smem_set = 0;
    if (!smem_set) {
        cudaFuncSetAttribute(wave_kernel, cudaFuncAttributeMaxDynamicSharedMemorySize,
                             DYN_SMEM);
        smem_set = 1;
    }

    cudaMemsetAsync(bar, 0, sizeof(unsigned));

    transpose_x<<<(T_ * B_ * (I_ / 4)) / 256, 256>>>(x, XT);

    // layer-0 input projection (fp32, K=64): XP = XT @ W_ih0^T + b_ih0
    gemm_nt<128, 64, 16, 8, 4><<<dim3(H_ / 64, (T_ * B_) / 128), 256>>>(
        XT, W_ih0, b_ih0, XP, T_ * B_, H_, I_);

    // merged weight hi/lo split (fp16 digits)
    {
        const size_t total = (size_t)H_ * H_ + (size_t)3 * H_ * K2_;
        prep_weights<<<(unsigned)(total / 256), 256>>>(W_hh, W_ihr, W0h, W0l, Wch, Wcl);
    }

    // wavefront over all layers/time
    wave_kernel<<<128, WTHREADS, DYN_SMEM>>>(XP, b_ihr);

    // final FC from h^{L-1}_{T-1} (parity (T-1)&1 = 1)
    fc_kernel<<<B_, 256>>>(Hh + (size_t)(3 * 2 + 1) * BH_,
                           Hl + (size_t)(3 * 2 + 1) * BH_, W_fc, b_fc, out);
}